// round 12
// baseline (speedup 1.0000x reference)
#include <cuda_runtime.h>
#include <cuda_bf16.h>
#include <math.h>
#include <stdint.h>

#define NN 4096
#define IN_DIM 256
#define HIDDEN 512
#define CLASSES 256
#define HEADS 4
#define HD 64
#define EE 131072

// ---------------- scratch ----------------
#define OFF_DINV   0L
#define OFF_AGGX   (OFF_DINV + NN)
#define OFF_AGG1   (OFF_AGGX + (long)NN * IN_DIM)
#define OFF_H2     (OFF_AGG1 + (long)NN * HIDDEN)
#define OFF_COMBO  (OFF_H2   + (long)NN * HIDDEN)
#define OFF_COMBOW (OFF_COMBO + (long)NN * 768)
#define OFF_BTOT   (OFF_COMBOW + 768L * 256)
#define SCRATCH_TOTAL (OFF_BTOT + 256)

__device__ __align__(16) float g_scratch[SCRATCH_TOTAL];
__device__ __align__(16) __nv_bfloat16 g_qkvh[(long)NN * 3 * IN_DIM];
__device__ int g_cnt[NN];
__device__ int g_rowptr[NN + 1];
__device__ int g_srcidx[EE];

// ---------------- CSR build ----------------
__global__ void zero_cnt_kernel() {
    int i = blockIdx.x * blockDim.x + threadIdx.x;
    if (i < NN) g_cnt[i] = 0;
}
__global__ void hist_kernel(const int* __restrict__ ei) {
    int i = blockIdx.x * blockDim.x + threadIdx.x;
    if (i < EE) atomicAdd(&g_cnt[ei[EE + i]], 1);
}
__global__ __launch_bounds__(1024) void scan_kernel() {
    __shared__ int sh[1024];
    int t = threadIdx.x;
    int base = t * 4;
    int c0 = g_cnt[base + 0], c1 = g_cnt[base + 1];
    int c2 = g_cnt[base + 2], c3 = g_cnt[base + 3];
    int s = c0 + c1 + c2 + c3;
    sh[t] = s;
    __syncthreads();
    for (int off = 1; off < 1024; off <<= 1) {
        int v = (t >= off) ? sh[t - off] : 0;
        __syncthreads();
        sh[t] += v;
        __syncthreads();
    }
    int run = sh[t] - s;
    g_rowptr[base + 0] = run;            run += c0;
    g_rowptr[base + 1] = run;            run += c1;
    g_rowptr[base + 2] = run;            run += c2;
    g_rowptr[base + 3] = run;            run += c3;
    if (t == 1023) g_rowptr[NN] = run;
    g_scratch[OFF_DINV + base + 0] = rsqrtf((float)c0 + 1.0f);
    g_scratch[OFF_DINV + base + 1] = rsqrtf((float)c1 + 1.0f);
    g_scratch[OFF_DINV + base + 2] = rsqrtf((float)c2 + 1.0f);
    g_scratch[OFF_DINV + base + 3] = rsqrtf((float)c3 + 1.0f);
    g_cnt[base + 0] = 0; g_cnt[base + 1] = 0;
    g_cnt[base + 2] = 0; g_cnt[base + 3] = 0;
}
__global__ void fill_kernel(const int* __restrict__ ei) {
    int e = blockIdx.x * blockDim.x + threadIdx.x;
    if (e >= EE) return;
    int dst = ei[EE + e];
    int pos = g_rowptr[dst] + atomicAdd(&g_cnt[dst], 1);
    g_srcidx[pos] = ei[e];
}

// ---------------- fused GCN aggregation (gather) ----------------
// out[node, coloff+c] = (opt relu/bias)( h[node]*dinv^2 (+bias) + sum_nbr h[src]*w )
template <bool BIASRELU>
__global__ __launch_bounds__(256) void gather_kernel(const float* __restrict__ hext, long hoff,
                                                     const float* __restrict__ bias,
                                                     long aggoff, int F, int ostride, int coloff) {
    const float* __restrict__ h = hext ? hext : (const float*)(g_scratch + hoff);
    float* __restrict__ agg = g_scratch + aggoff;
    const float* __restrict__ dinv = g_scratch + OFF_DINV;
    const int warp = threadIdx.x >> 5;
    const int lane = threadIdx.x & 31;
    const int node = blockIdx.x * 8 + warp;
    const int c = blockIdx.y * 128 + lane * 4;

    float dd = dinv[node];
    float4 hv = *(const float4*)&h[(size_t)node * F + c];
    float sw = dd * dd;
    float4 acc = make_float4(hv.x * sw, hv.y * sw, hv.z * sw, hv.w * sw);
    if (BIASRELU) {
        float4 b4 = *(const float4*)&bias[c];
        acc.x += b4.x; acc.y += b4.y; acc.z += b4.z; acc.w += b4.w;
    }

    int beg = g_rowptr[node];
    int end = g_rowptr[node + 1];
    for (int j = beg; j < end; j++) {
        int src = g_srcidx[j];
        float w = dinv[src] * dd;
        float4 v = *(const float4*)&h[(size_t)src * F + c];
        acc.x += v.x * w; acc.y += v.y * w;
        acc.z += v.z * w; acc.w += v.w * w;
    }
    if (BIASRELU) {
        acc.x = fmaxf(acc.x, 0.0f); acc.y = fmaxf(acc.y, 0.0f);
        acc.z = fmaxf(acc.z, 0.0f); acc.w = fmaxf(acc.w, 0.0f);
    }
    *(float4*)&agg[(size_t)node * ostride + coloff + c] = acc;
}

// ---------------- epilogue-fold prep kernels ----------------
// comboW rows 0:512 = lin_w
__global__ void copy_linw_kernel(const float* __restrict__ lin_w) {
    int i = blockIdx.x * blockDim.x + threadIdx.x;  // over 512*256/4
    float4 v = *(const float4*)&lin_w[4L * i];
    *(float4*)&g_scratch[OFF_COMBOW + 4L * i] = v;
}
// comboW rows 512:768 : W'[i,j] = sum_k out_w[k,i] * proj_w[k,j]
__global__ __launch_bounds__(256) void wprime_kernel(const float* __restrict__ out_w,
                                                     const float* __restrict__ proj_w) {
    int i = blockIdx.x;
    int j = threadIdx.x;
    float acc = 0.0f;
#pragma unroll 4
    for (int k = 0; k < 256; k++)
        acc += __ldg(&out_w[k * 256 + i]) * proj_w[k * 256 + j];
    g_scratch[OFF_COMBOW + (512L + i) * 256 + j] = acc;
}
// b_tot[j] = lin_b[j] + proj_b[j] + sum_k out_b[k] * proj_w[k,j]
__global__ __launch_bounds__(256) void btot_kernel(const float* __restrict__ lin_b,
                                                   const float* __restrict__ out_b,
                                                   const float* __restrict__ proj_w,
                                                   const float* __restrict__ proj_b) {
    int j = threadIdx.x;
    float acc = lin_b[j] + proj_b[j];
#pragma unroll 4
    for (int k = 0; k < 256; k++)
        acc += __ldg(&out_b[k]) * proj_w[k * 256 + j];
    g_scratch[OFF_BTOT + j] = acc;
}

// ---------------- tf32 helpers ----------------
__device__ __forceinline__ float to_tf32(float x) {
    float r;
    asm("cvt.rna.tf32.f32 %0, %1;" : "=f"(r) : "f"(x));
    return r;
}
__device__ __forceinline__ void mma_tf32(float c[4], float a0, float a1, float a2,
                                         float a3, float b0, float b1) {
    uint32_t ua0 = __float_as_uint(a0), ua1 = __float_as_uint(a1);
    uint32_t ua2 = __float_as_uint(a2), ua3 = __float_as_uint(a3);
    uint32_t ub0 = __float_as_uint(b0), ub1 = __float_as_uint(b1);
    asm volatile(
        "mma.sync.aligned.m16n8k8.row.col.f32.tf32.tf32.f32 "
        "{%0,%1,%2,%3},{%4,%5,%6,%7},{%8,%9},{%0,%1,%2,%3};\n"
        : "+f"(c[0]), "+f"(c[1]), "+f"(c[2]), "+f"(c[3])
        : "r"(ua0), "r"(ua1), "r"(ua2), "r"(ua3), "r"(ub0), "r"(ub1));
}

// ---------------- tf32 tensor-core GEMM, double buffered ----------------
#define AP 20
#define BPN 72
#define BPT 20
template <bool TRANSB, bool RELU, bool HASBIAS, bool OUTBF16>
__global__ __launch_bounds__(256) void gemm_tc(const float* __restrict__ Aext, long aoff,
                                               const float* __restrict__ Bext, long boff,
                                               const float* __restrict__ biasext, long biasoff,
                                               float* __restrict__ Cext, long coff,
                                               int M, int K, int Nd) {
    const float* __restrict__ A = Aext ? Aext : (const float*)(g_scratch + aoff);
    const float* __restrict__ B = Bext ? Bext : (const float*)(g_scratch + boff);
    const float* __restrict__ bias = HASBIAS ? (biasext ? biasext : (const float*)(g_scratch + biasoff)) : nullptr;
    float* __restrict__ C = Cext ? Cext : (g_scratch + coff);

    constexpr int BSZ = TRANSB ? 64 * BPT : 16 * BPN;
    __shared__ float As[2][128][AP];
    __shared__ float Bs[2][BSZ];

    const int tid = threadIdx.x;
    const int warp = tid >> 5, lane = tid & 31;
    const int fr = lane >> 2, fc = lane & 3;
    const int mw = warp * 16;
    const int m0 = blockIdx.y * 128, n0 = blockIdx.x * 64;

    const int akq = (tid & 3) * 4;
    const int bn = tid >> 2;
    const int bkq = (tid & 3) * 4;
    const int bkr = tid >> 4;
    const int bn4 = (tid & 15) * 4;

    float4 pa0, pa1, pb;
    {
        int m_a0 = tid >> 2, m_a1 = 64 + (tid >> 2);
        pa0 = *(const float4*)(A + (size_t)(m0 + m_a0) * K + akq);
        pa1 = *(const float4*)(A + (size_t)(m0 + m_a1) * K + akq);
        if (TRANSB)
            pb = *(const float4*)(B + (size_t)(n0 + bn) * K + bkq);
        else
            pb = *(const float4*)(B + (size_t)bkr * Nd + n0 + bn4);
    }

    float acc[8][4];
#pragma unroll
    for (int nt = 0; nt < 8; nt++)
#pragma unroll
        for (int j = 0; j < 4; j++) acc[nt][j] = 0.0f;

    const int nk = K >> 4;
    {
        int m_a0 = tid >> 2, m_a1 = 64 + (tid >> 2);
        As[0][m_a0][akq + 0] = to_tf32(pa0.x);
        As[0][m_a0][akq + 1] = to_tf32(pa0.y);
        As[0][m_a0][akq + 2] = to_tf32(pa0.z);
        As[0][m_a0][akq + 3] = to_tf32(pa0.w);
        As[0][m_a1][akq + 0] = to_tf32(pa1.x);
        As[0][m_a1][akq + 1] = to_tf32(pa1.y);
        As[0][m_a1][akq + 2] = to_tf32(pa1.z);
        As[0][m_a1][akq + 3] = to_tf32(pa1.w);
        if (TRANSB) {
            float* bp = &Bs[0][bn * BPT + bkq];
            bp[0] = to_tf32(pb.x); bp[1] = to_tf32(pb.y);
            bp[2] = to_tf32(pb.z); bp[3] = to_tf32(pb.w);
        } else {
            float* bp = &Bs[0][bkr * BPN + bn4];
            bp[0] = to_tf32(pb.x); bp[1] = to_tf32(pb.y);
            bp[2] = to_tf32(pb.z); bp[3] = to_tf32(pb.w);
        }
    }
    __syncthreads();

    for (int k0i = 0; k0i < nk; k0i++) {
        const int cur = k0i & 1, nxt = cur ^ 1;
        const bool more = (k0i + 1) < nk;
        if (more) {
            int k0 = (k0i + 1) << 4;
            int m_a0 = tid >> 2, m_a1 = 64 + (tid >> 2);
            pa0 = *(const float4*)(A + (size_t)(m0 + m_a0) * K + k0 + akq);
            pa1 = *(const float4*)(A + (size_t)(m0 + m_a1) * K + k0 + akq);
            if (TRANSB)
                pb = *(const float4*)(B + (size_t)(n0 + bn) * K + k0 + bkq);
            else
                pb = *(const float4*)(B + (size_t)(k0 + bkr) * Nd + n0 + bn4);
        }

#pragma unroll
        for (int ks = 0; ks < 2; ks++) {
            int kk = ks * 8;
            float a0 = As[cur][mw + fr][kk + fc];
            float a1 = As[cur][mw + fr + 8][kk + fc];
            float a2 = As[cur][mw + fr][kk + fc + 4];
            float a3 = As[cur][mw + fr + 8][kk + fc + 4];
#pragma unroll
            for (int nt = 0; nt < 8; nt++) {
                float b0, b1;
                if (TRANSB) {
                    b0 = Bs[cur][(nt * 8 + fr) * BPT + kk + fc];
                    b1 = Bs[cur][(nt * 8 + fr) * BPT + kk + fc + 4];
                } else {
                    b0 = Bs[cur][(kk + fc) * BPN + nt * 8 + fr];
                    b1 = Bs[cur][(kk + fc + 4) * BPN + nt * 8 + fr];
                }
                mma_tf32(acc[nt], a0, a1, a2, a3, b0, b1);
            }
        }

        if (more) {
            int m_a0 = tid >> 2, m_a1 = 64 + (tid >> 2);
            As[nxt][m_a0][akq + 0] = to_tf32(pa0.x);
            As[nxt][m_a0][akq + 1] = to_tf32(pa0.y);
            As[nxt][m_a0][akq + 2] = to_tf32(pa0.z);
            As[nxt][m_a0][akq + 3] = to_tf32(pa0.w);
            As[nxt][m_a1][akq + 0] = to_tf32(pa1.x);
            As[nxt][m_a1][akq + 1] = to_tf32(pa1.y);
            As[nxt][m_a1][akq + 2] = to_tf32(pa1.z);
            As[nxt][m_a1][akq + 3] = to_tf32(pa1.w);
            if (TRANSB) {
                float* bp = &Bs[nxt][bn * BPT + bkq];
                bp[0] = to_tf32(pb.x); bp[1] = to_tf32(pb.y);
                bp[2] = to_tf32(pb.z); bp[3] = to_tf32(pb.w);
            } else {
                float* bp = &Bs[nxt][bkr * BPN + bn4];
                bp[0] = to_tf32(pb.x); bp[1] = to_tf32(pb.y);
                bp[2] = to_tf32(pb.z); bp[3] = to_tf32(pb.w);
            }
            __syncthreads();
        }
    }

    int r0 = m0 + mw + fr;
    int r1 = r0 + 8;
#pragma unroll
    for (int nt = 0; nt < 8; nt++) {
        int cc = n0 + nt * 8 + fc * 2;
        float v00 = acc[nt][0], v01 = acc[nt][1];
        float v10 = acc[nt][2], v11 = acc[nt][3];
        if (HASBIAS) {
            float b0 = bias[cc], b1 = bias[cc + 1];
            v00 += b0; v01 += b1; v10 += b0; v11 += b1;
        }
        if (RELU) {
            v00 = fmaxf(v00, 0.0f); v01 = fmaxf(v01, 0.0f);
            v10 = fmaxf(v10, 0.0f); v11 = fmaxf(v11, 0.0f);
        }
        if (OUTBF16) {
            __nv_bfloat162 h0 = __floats2bfloat162_rn(v00, v01);
            __nv_bfloat162 h1 = __floats2bfloat162_rn(v10, v11);
            *(uint32_t*)&g_qkvh[(size_t)r0 * Nd + cc] = *(uint32_t*)&h0;
            *(uint32_t*)&g_qkvh[(size_t)r1 * Nd + cc] = *(uint32_t*)&h1;
        } else {
            *(float2*)&C[(size_t)r0 * Nd + cc] = make_float2(v00, v01);
            *(float2*)&C[(size_t)r1 * Nd + cc] = make_float2(v10, v11);
        }
    }
}

// ---------------- bf16 tensor-core flash attention ----------------
__device__ __forceinline__ void mma_bf16(float c[4], uint32_t a0, uint32_t a1,
                                         uint32_t a2, uint32_t a3,
                                         uint32_t b0, uint32_t b1) {
    asm volatile(
        "mma.sync.aligned.m16n8k16.row.col.f32.bf16.bf16.f32 "
        "{%0,%1,%2,%3},{%4,%5,%6,%7},{%8,%9},{%0,%1,%2,%3};\n"
        : "+f"(c[0]), "+f"(c[1]), "+f"(c[2]), "+f"(c[3])
        : "r"(a0), "r"(a1), "r"(a2), "r"(a3), "r"(b0), "r"(b1));
}

#define FA_PITCH 72

// writes output into combo buffer: row stride 768, column offset 512
__global__ __launch_bounds__(128) void flash_attn_bf16_kernel() {
    const __nv_bfloat16* __restrict__ qkvh = g_qkvh;
    float* __restrict__ outp = g_scratch + OFF_COMBO + 512;
    const int head = blockIdx.y;
    const int q0 = blockIdx.x * 64;
    const int tid = threadIdx.x;
    const int warp = tid >> 5;
    const int lane = tid & 31;
    const int quad = lane >> 2;
    const int qd = lane & 3;

    __shared__ __align__(16) __nv_bfloat16 Qs[64][FA_PITCH];
    __shared__ __align__(16) __nv_bfloat16 Ks[64][FA_PITCH];
    __shared__ __align__(16) __nv_bfloat16 Vt[64][FA_PITCH];
    __shared__ __align__(16) __nv_bfloat16 Ps[64][FA_PITCH];

#pragma unroll
    for (int ch = 0; ch < 4; ch++) {
        int idx = ch * 128 + tid;
        int r = idx >> 3;
        int c = (idx & 7) * 8;
        *(uint4*)&Qs[r][c] =
            *(const uint4*)&qkvh[(size_t)(q0 + r) * 768 + head * 64 + c];
    }

    float m0r = -1e30f, m1r = -1e30f;
    float l0r = 0.0f, l1r = 0.0f;
    float o[8][4];
#pragma unroll
    for (int nt = 0; nt < 8; nt++)
#pragma unroll
        for (int j = 0; j < 4; j++) o[nt][j] = 0.0f;

    const int qrowA = warp * 16 + quad;
    const int qrowB = qrowA + 8;

    for (int kb = 0; kb < NN / 64; kb++) {
        int kbase = kb * 64;
        __syncthreads();
#pragma unroll
        for (int ch = 0; ch < 4; ch++) {
            int idx = ch * 128 + tid;
            int r = idx >> 3;
            int c = (idx & 7) * 8;
            *(uint4*)&Ks[r][c] =
                *(const uint4*)&qkvh[(size_t)(kbase + r) * 768 + 256 + head * 64 + c];
        }
        {
            int r = tid & 63;
            int d0 = (tid >> 6) * 32;
#pragma unroll
            for (int u = 0; u < 4; u++) {
                uint4 vv = *(const uint4*)&qkvh[(size_t)(kbase + r) * 768 + 512 +
                                                head * 64 + d0 + u * 8];
                __nv_bfloat16 tmp[8];
                *(uint4*)tmp = vv;
#pragma unroll
                for (int j = 0; j < 8; j++) Vt[d0 + u * 8 + j][r] = tmp[j];
            }
        }
        __syncthreads();

        float sc[8][4];
#pragma unroll
        for (int nt = 0; nt < 8; nt++)
#pragma unroll
            for (int j = 0; j < 4; j++) sc[nt][j] = 0.0f;

#pragma unroll
        for (int ks = 0; ks < 4; ks++) {
            int k0 = ks * 16;
            uint32_t a0 = *(const uint32_t*)&Qs[qrowA][k0 + qd * 2];
            uint32_t a1 = *(const uint32_t*)&Qs[qrowB][k0 + qd * 2];
            uint32_t a2 = *(const uint32_t*)&Qs[qrowA][k0 + qd * 2 + 8];
            uint32_t a3 = *(const uint32_t*)&Qs[qrowB][k0 + qd * 2 + 8];
#pragma unroll
            for (int nt = 0; nt < 8; nt++) {
                uint32_t b0 = *(const uint32_t*)&Ks[nt * 8 + quad][k0 + qd * 2];
                uint32_t b1 = *(const uint32_t*)&Ks[nt * 8 + quad][k0 + qd * 2 + 8];
                mma_bf16(sc[nt], a0, a1, a2, a3, b0, b1);
            }
        }

        float mA = -1e30f, mB = -1e30f;
#pragma unroll
        for (int nt = 0; nt < 8; nt++) {
            sc[nt][0] *= 0.125f; sc[nt][1] *= 0.125f;
            sc[nt][2] *= 0.125f; sc[nt][3] *= 0.125f;
            mA = fmaxf(mA, fmaxf(sc[nt][0], sc[nt][1]));
            mB = fmaxf(mB, fmaxf(sc[nt][2], sc[nt][3]));
        }
        mA = fmaxf(mA, __shfl_xor_sync(0xffffffffu, mA, 1));
        mA = fmaxf(mA, __shfl_xor_sync(0xffffffffu, mA, 2));
        mB = fmaxf(mB, __shfl_xor_sync(0xffffffffu, mB, 1));
        mB = fmaxf(mB, __shfl_xor_sync(0xffffffffu, mB, 2));
        float mnA = fmaxf(m0r, mA);
        float mnB = fmaxf(m1r, mB);
        float alA = __expf(m0r - mnA);
        float alB = __expf(m1r - mnB);
        float sumA = 0.0f, sumB = 0.0f;
#pragma unroll
        for (int nt = 0; nt < 8; nt++) {
            float p0 = __expf(sc[nt][0] - mnA);
            float p1 = __expf(sc[nt][1] - mnA);
            float p2 = __expf(sc[nt][2] - mnB);
            float p3 = __expf(sc[nt][3] - mnB);
            sumA += p0 + p1;
            sumB += p2 + p3;
            __nv_bfloat162 hA = __floats2bfloat162_rn(p0, p1);
            __nv_bfloat162 hB = __floats2bfloat162_rn(p2, p3);
            *(uint32_t*)&Ps[qrowA][nt * 8 + qd * 2] = *(uint32_t*)&hA;
            *(uint32_t*)&Ps[qrowB][nt * 8 + qd * 2] = *(uint32_t*)&hB;
        }
        sumA += __shfl_xor_sync(0xffffffffu, sumA, 1);
        sumA += __shfl_xor_sync(0xffffffffu, sumA, 2);
        sumB += __shfl_xor_sync(0xffffffffu, sumB, 1);
        sumB += __shfl_xor_sync(0xffffffffu, sumB, 2);
        l0r = l0r * alA + sumA;
        l1r = l1r * alB + sumB;
        m0r = mnA;
        m1r = mnB;
#pragma unroll
        for (int nt = 0; nt < 8; nt++) {
            o[nt][0] *= alA; o[nt][1] *= alA;
            o[nt][2] *= alB; o[nt][3] *= alB;
        }
        __syncwarp();

#pragma unroll
        for (int ks = 0; ks < 4; ks++) {
            int k0 = ks * 16;
            uint32_t a0 = *(const uint32_t*)&Ps[qrowA][k0 + qd * 2];
            uint32_t a1 = *(const uint32_t*)&Ps[qrowB][k0 + qd * 2];
            uint32_t a2 = *(const uint32_t*)&Ps[qrowA][k0 + qd * 2 + 8];
            uint32_t a3 = *(const uint32_t*)&Ps[qrowB][k0 + qd * 2 + 8];
#pragma unroll
            for (int nt = 0; nt < 8; nt++) {
                uint32_t b0 = *(const uint32_t*)&Vt[nt * 8 + quad][k0 + qd * 2];
                uint32_t b1 = *(const uint32_t*)&Vt[nt * 8 + quad][k0 + qd * 2 + 8];
                mma_bf16(o[nt], a0, a1, a2, a3, b0, b1);
            }
        }
    }

    float invA = 1.0f / l0r;
    float invB = 1.0f / l1r;
    int gA = q0 + qrowA;
    int gB = q0 + qrowB;
#pragma unroll
    for (int nt = 0; nt < 8; nt++) {
        float2 vA = make_float2(o[nt][0] * invA, o[nt][1] * invA);
        float2 vB = make_float2(o[nt][2] * invB, o[nt][3] * invB);
        *(float2*)&outp[(size_t)gA * 768 + head * 64 + nt * 8 + qd * 2] = vA;
        *(float2*)&outp[(size_t)gB * 768 + head * 64 + nt * 8 + qd * 2] = vB;
    }
}

// ---------------- launch ----------------
extern "C" void kernel_launch(void* const* d_in, const int* in_sizes, int n_in,
                              void* d_out, int out_size) {
    const float* x          = (const float*)d_in[0];
    const int*   ei         = (const int*)d_in[1];
    const float* gcn1_w     = (const float*)d_in[2];
    const float* gcn1_b     = (const float*)d_in[3];
    const float* gcn2_w     = (const float*)d_in[4];
    const float* gcn2_b     = (const float*)d_in[5];
    const float* lin_w      = (const float*)d_in[6];
    const float* lin_b      = (const float*)d_in[7];
    const float* in_proj_w  = (const float*)d_in[8];
    const float* in_proj_b  = (const float*)d_in[9];
    const float* out_proj_w = (const float*)d_in[10];
    const float* out_proj_b = (const float*)d_in[11];
    const float* proj_w     = (const float*)d_in[12];
    const float* proj_b     = (const float*)d_in[13];
    float* out = (float*)d_out;

    cudaStream_t s2;
    cudaStreamCreateWithFlags(&s2, cudaStreamNonBlocking);
    cudaEvent_t eFork, eJoin;
    cudaEventCreateWithFlags(&eFork, cudaEventDisableTiming);
    cudaEventCreateWithFlags(&eJoin, cudaEventDisableTiming);

    cudaEventRecord(eFork, 0);
    cudaStreamWaitEvent(s2, eFork, 0);

    // ---- stream s2: weight folding + transformer branch ----
    copy_linw_kernel<<<(HIDDEN * CLASSES / 4) / 256, 256, 0, s2>>>(lin_w);
    wprime_kernel<<<256, 256, 0, s2>>>(out_proj_w, proj_w);
    btot_kernel<<<1, 256, 0, s2>>>(lin_b, out_proj_b, proj_w, proj_b);
    gemm_tc<true, false, true, true><<<dim3((3 * IN_DIM) / 64, NN / 128), 256, 0, s2>>>(
        x, 0L, in_proj_w, 0L, in_proj_b, 0L, nullptr, 0L, NN, IN_DIM, 3 * IN_DIM);
    flash_attn_bf16_kernel<<<dim3(NN / 64, HEADS), 128, 0, s2>>>();
    cudaEventRecord(eJoin, s2);

    // ---- default stream: CSR build + GNN branch ----
    zero_cnt_kernel<<<NN / 256, 256>>>();
    hist_kernel<<<EE / 256, 256>>>(ei);
    scan_kernel<<<1, 1024>>>();
    fill_kernel<<<EE / 256, 256>>>(ei);

    // aggregate-first conv1: aggx = A_hat @ x  (no bias/relu)
    gather_kernel<false><<<dim3(NN / 8, IN_DIM / 128), 256>>>(
        x, 0L, nullptr, OFF_AGGX, IN_DIM, IN_DIM, 0);
    // agg1 = relu(aggx @ W1 + b1)
    gemm_tc<false, true, true, false><<<dim3(HIDDEN / 64, NN / 128), 256>>>(
        nullptr, OFF_AGGX, gcn1_w, 0L, gcn1_b, 0L, nullptr, OFF_AGG1, NN, IN_DIM, HIDDEN);

    // h2 = agg1 @ W2
    gemm_tc<false, false, false, false><<<dim3(HIDDEN / 64, NN / 128), 256>>>(
        nullptr, OFF_AGG1, gcn2_w, 0L, nullptr, 0L, nullptr, OFF_H2, NN, HIDDEN, HIDDEN);
    // combo[:, 0:512] = relu(A_hat @ h2 + b2)
    gather_kernel<true><<<dim3(NN / 8, HIDDEN / 128), 256>>>(
        nullptr, OFF_H2, gcn2_b, OFF_COMBO, HIDDEN, 768, 0);

    // ---- join: out = relu([agg2 | attn] @ comboW + b_tot) ----
    cudaStreamWaitEvent(0, eJoin, 0);
    gemm_tc<false, true, true, false><<<dim3(CLASSES / 64, NN / 128), 256>>>(
        nullptr, OFF_COMBO, nullptr, OFF_COMBOW, nullptr, OFF_BTOT, out, 0L, NN, 768, CLASSES);
}

// round 13
// speedup vs baseline: 1.2028x; 1.2028x over previous
#include <cuda_runtime.h>
#include <cuda_bf16.h>
#include <math.h>
#include <stdint.h>

#define NN 4096
#define IN_DIM 256
#define HIDDEN 512
#define CLASSES 256
#define HEADS 4
#define HD 64
#define EE 131072

// ---------------- scratch ----------------
#define OFF_DINV   0L
#define OFF_AGGX   (OFF_DINV + NN)
#define OFF_AGG1   (OFF_AGGX + (long)NN * IN_DIM)
#define OFF_H2     (OFF_AGG1 + (long)NN * HIDDEN)
#define OFF_COMBO  (OFF_H2   + (long)NN * HIDDEN)
#define OFF_COMBOW (OFF_COMBO + (long)NN * 768)
#define OFF_BTOT   (OFF_COMBOW + 768L * 256)
#define SCRATCH_TOTAL (OFF_BTOT + 256)

__device__ __align__(16) float g_scratch[SCRATCH_TOTAL];
__device__ __align__(16) __nv_bfloat16 g_qkvh[(long)NN * 3 * IN_DIM];
__device__ int g_cnt[NN];
__device__ int g_rowptr[NN + 1];
__device__ int g_srcidx[EE];

// ---------------- CSR build ----------------
__global__ void zero_cnt_kernel() {
    int i = blockIdx.x * blockDim.x + threadIdx.x;
    if (i < NN) g_cnt[i] = 0;
}
__global__ void hist_kernel(const int* __restrict__ ei) {
    int i = blockIdx.x * blockDim.x + threadIdx.x;
    if (i < EE) atomicAdd(&g_cnt[ei[EE + i]], 1);
}
__global__ __launch_bounds__(1024) void scan_kernel() {
    __shared__ int sh[1024];
    int t = threadIdx.x;
    int base = t * 4;
    int c0 = g_cnt[base + 0], c1 = g_cnt[base + 1];
    int c2 = g_cnt[base + 2], c3 = g_cnt[base + 3];
    int s = c0 + c1 + c2 + c3;
    sh[t] = s;
    __syncthreads();
    for (int off = 1; off < 1024; off <<= 1) {
        int v = (t >= off) ? sh[t - off] : 0;
        __syncthreads();
        sh[t] += v;
        __syncthreads();
    }
    int run = sh[t] - s;
    g_rowptr[base + 0] = run;            run += c0;
    g_rowptr[base + 1] = run;            run += c1;
    g_rowptr[base + 2] = run;            run += c2;
    g_rowptr[base + 3] = run;            run += c3;
    if (t == 1023) g_rowptr[NN] = run;
    g_scratch[OFF_DINV + base + 0] = rsqrtf((float)c0 + 1.0f);
    g_scratch[OFF_DINV + base + 1] = rsqrtf((float)c1 + 1.0f);
    g_scratch[OFF_DINV + base + 2] = rsqrtf((float)c2 + 1.0f);
    g_scratch[OFF_DINV + base + 3] = rsqrtf((float)c3 + 1.0f);
    g_cnt[base + 0] = 0; g_cnt[base + 1] = 0;
    g_cnt[base + 2] = 0; g_cnt[base + 3] = 0;
}
__global__ void fill_kernel(const int* __restrict__ ei) {
    int e = blockIdx.x * blockDim.x + threadIdx.x;
    if (e >= EE) return;
    int dst = ei[EE + e];
    int pos = g_rowptr[dst] + atomicAdd(&g_cnt[dst], 1);
    g_srcidx[pos] = ei[e];
}

// ---------------- fused GCN aggregation (gather) ----------------
template <bool BIASRELU>
__global__ __launch_bounds__(256) void gather_kernel(const float* __restrict__ hext, long hoff,
                                                     const float* __restrict__ bias,
                                                     long aggoff, int F, int ostride, int coloff) {
    const float* __restrict__ h = hext ? hext : (const float*)(g_scratch + hoff);
    float* __restrict__ agg = g_scratch + aggoff;
    const float* __restrict__ dinv = g_scratch + OFF_DINV;
    const int warp = threadIdx.x >> 5;
    const int lane = threadIdx.x & 31;
    const int node = blockIdx.x * 8 + warp;
    const int c = blockIdx.y * 128 + lane * 4;

    float dd = dinv[node];
    float4 hv = *(const float4*)&h[(size_t)node * F + c];
    float sw = dd * dd;
    float4 acc = make_float4(hv.x * sw, hv.y * sw, hv.z * sw, hv.w * sw);
    if (BIASRELU) {
        float4 b4 = *(const float4*)&bias[c];
        acc.x += b4.x; acc.y += b4.y; acc.z += b4.z; acc.w += b4.w;
    }

    int beg = g_rowptr[node];
    int end = g_rowptr[node + 1];
    int j = beg;
    for (; j + 2 <= end; j += 2) {
        int s0 = g_srcidx[j];
        int s1 = g_srcidx[j + 1];
        float w0 = dinv[s0] * dd;
        float w1 = dinv[s1] * dd;
        float4 v0 = *(const float4*)&h[(size_t)s0 * F + c];
        float4 v1 = *(const float4*)&h[(size_t)s1 * F + c];
        acc.x += v0.x * w0 + v1.x * w1;
        acc.y += v0.y * w0 + v1.y * w1;
        acc.z += v0.z * w0 + v1.z * w1;
        acc.w += v0.w * w0 + v1.w * w1;
    }
    if (j < end) {
        int s0 = g_srcidx[j];
        float w0 = dinv[s0] * dd;
        float4 v0 = *(const float4*)&h[(size_t)s0 * F + c];
        acc.x += v0.x * w0; acc.y += v0.y * w0;
        acc.z += v0.z * w0; acc.w += v0.w * w0;
    }
    if (BIASRELU) {
        acc.x = fmaxf(acc.x, 0.0f); acc.y = fmaxf(acc.y, 0.0f);
        acc.z = fmaxf(acc.z, 0.0f); acc.w = fmaxf(acc.w, 0.0f);
    }
    *(float4*)&agg[(size_t)node * ostride + coloff + c] = acc;
}

// ---------------- epilogue-fold prep kernels ----------------
__global__ void copy_linw_kernel(const float* __restrict__ lin_w) {
    int i = blockIdx.x * blockDim.x + threadIdx.x;
    float4 v = *(const float4*)&lin_w[4L * i];
    *(float4*)&g_scratch[OFF_COMBOW + 4L * i] = v;
}
__global__ __launch_bounds__(256) void wprime_kernel(const float* __restrict__ out_w,
                                                     const float* __restrict__ proj_w) {
    int i = blockIdx.x;
    int j = threadIdx.x;
    float acc = 0.0f;
#pragma unroll 4
    for (int k = 0; k < 256; k++)
        acc += __ldg(&out_w[k * 256 + i]) * proj_w[k * 256 + j];
    g_scratch[OFF_COMBOW + (512L + i) * 256 + j] = acc;
}
__global__ __launch_bounds__(256) void btot_kernel(const float* __restrict__ lin_b,
                                                   const float* __restrict__ out_b,
                                                   const float* __restrict__ proj_w,
                                                   const float* __restrict__ proj_b) {
    int j = threadIdx.x;
    float acc = lin_b[j] + proj_b[j];
#pragma unroll 4
    for (int k = 0; k < 256; k++)
        acc += __ldg(&out_b[k]) * proj_w[k * 256 + j];
    g_scratch[OFF_BTOT + j] = acc;
}

// ---------------- tf32 helpers ----------------
__device__ __forceinline__ float to_tf32(float x) {
    float r;
    asm("cvt.rna.tf32.f32 %0, %1;" : "=f"(r) : "f"(x));
    return r;
}
__device__ __forceinline__ void mma_tf32(float c[4], float a0, float a1, float a2,
                                         float a3, float b0, float b1) {
    uint32_t ua0 = __float_as_uint(a0), ua1 = __float_as_uint(a1);
    uint32_t ua2 = __float_as_uint(a2), ua3 = __float_as_uint(a3);
    uint32_t ub0 = __float_as_uint(b0), ub1 = __float_as_uint(b1);
    asm volatile(
        "mma.sync.aligned.m16n8k8.row.col.f32.tf32.tf32.f32 "
        "{%0,%1,%2,%3},{%4,%5,%6,%7},{%8,%9},{%0,%1,%2,%3};\n"
        : "+f"(c[0]), "+f"(c[1]), "+f"(c[2]), "+f"(c[3])
        : "r"(ua0), "r"(ua1), "r"(ua2), "r"(ua3), "r"(ub0), "r"(ub1));
}

// ---------------- tf32 tensor-core GEMM, double buffered ----------------
#define AP 20
#define BPN 72
#define BPT 20
template <bool TRANSB, bool RELU, bool HASBIAS, bool OUTBF16>
__global__ __launch_bounds__(256) void gemm_tc(const float* __restrict__ Aext, long aoff,
                                               const float* __restrict__ Bext, long boff,
                                               const float* __restrict__ biasext, long biasoff,
                                               float* __restrict__ Cext, long coff,
                                               int M, int K, int Nd) {
    const float* __restrict__ A = Aext ? Aext : (const float*)(g_scratch + aoff);
    const float* __restrict__ B = Bext ? Bext : (const float*)(g_scratch + boff);
    const float* __restrict__ bias = HASBIAS ? (biasext ? biasext : (const float*)(g_scratch + biasoff)) : nullptr;
    float* __restrict__ C = Cext ? Cext : (g_scratch + coff);

    constexpr int BSZ = TRANSB ? 64 * BPT : 16 * BPN;
    __shared__ float As[2][128][AP];
    __shared__ float Bs[2][BSZ];

    const int tid = threadIdx.x;
    const int warp = tid >> 5, lane = tid & 31;
    const int fr = lane >> 2, fc = lane & 3;
    const int mw = warp * 16;
    const int m0 = blockIdx.y * 128, n0 = blockIdx.x * 64;

    const int akq = (tid & 3) * 4;
    const int bn = tid >> 2;
    const int bkq = (tid & 3) * 4;
    const int bkr = tid >> 4;
    const int bn4 = (tid & 15) * 4;

    float4 pa0, pa1, pb;
    {
        int m_a0 = tid >> 2, m_a1 = 64 + (tid >> 2);
        pa0 = *(const float4*)(A + (size_t)(m0 + m_a0) * K + akq);
        pa1 = *(const float4*)(A + (size_t)(m0 + m_a1) * K + akq);
        if (TRANSB)
            pb = *(const float4*)(B + (size_t)(n0 + bn) * K + bkq);
        else
            pb = *(const float4*)(B + (size_t)bkr * Nd + n0 + bn4);
    }

    float acc[8][4];
#pragma unroll
    for (int nt = 0; nt < 8; nt++)
#pragma unroll
        for (int j = 0; j < 4; j++) acc[nt][j] = 0.0f;

    const int nk = K >> 4;
    {
        int m_a0 = tid >> 2, m_a1 = 64 + (tid >> 2);
        As[0][m_a0][akq + 0] = to_tf32(pa0.x);
        As[0][m_a0][akq + 1] = to_tf32(pa0.y);
        As[0][m_a0][akq + 2] = to_tf32(pa0.z);
        As[0][m_a0][akq + 3] = to_tf32(pa0.w);
        As[0][m_a1][akq + 0] = to_tf32(pa1.x);
        As[0][m_a1][akq + 1] = to_tf32(pa1.y);
        As[0][m_a1][akq + 2] = to_tf32(pa1.z);
        As[0][m_a1][akq + 3] = to_tf32(pa1.w);
        if (TRANSB) {
            float* bp = &Bs[0][bn * BPT + bkq];
            bp[0] = to_tf32(pb.x); bp[1] = to_tf32(pb.y);
            bp[2] = to_tf32(pb.z); bp[3] = to_tf32(pb.w);
        } else {
            float* bp = &Bs[0][bkr * BPN + bn4];
            bp[0] = to_tf32(pb.x); bp[1] = to_tf32(pb.y);
            bp[2] = to_tf32(pb.z); bp[3] = to_tf32(pb.w);
        }
    }
    __syncthreads();

    for (int k0i = 0; k0i < nk; k0i++) {
        const int cur = k0i & 1, nxt = cur ^ 1;
        const bool more = (k0i + 1) < nk;
        if (more) {
            int k0 = (k0i + 1) << 4;
            int m_a0 = tid >> 2, m_a1 = 64 + (tid >> 2);
            pa0 = *(const float4*)(A + (size_t)(m0 + m_a0) * K + k0 + akq);
            pa1 = *(const float4*)(A + (size_t)(m0 + m_a1) * K + k0 + akq);
            if (TRANSB)
                pb = *(const float4*)(B + (size_t)(n0 + bn) * K + k0 + bkq);
            else
                pb = *(const float4*)(B + (size_t)(k0 + bkr) * Nd + n0 + bn4);
        }

#pragma unroll
        for (int ks = 0; ks < 2; ks++) {
            int kk = ks * 8;
            float a0 = As[cur][mw + fr][kk + fc];
            float a1 = As[cur][mw + fr + 8][kk + fc];
            float a2 = As[cur][mw + fr][kk + fc + 4];
            float a3 = As[cur][mw + fr + 8][kk + fc + 4];
#pragma unroll
            for (int nt = 0; nt < 8; nt++) {
                float b0, b1;
                if (TRANSB) {
                    b0 = Bs[cur][(nt * 8 + fr) * BPT + kk + fc];
                    b1 = Bs[cur][(nt * 8 + fr) * BPT + kk + fc + 4];
                } else {
                    b0 = Bs[cur][(kk + fc) * BPN + nt * 8 + fr];
                    b1 = Bs[cur][(kk + fc + 4) * BPN + nt * 8 + fr];
                }
                mma_tf32(acc[nt], a0, a1, a2, a3, b0, b1);
            }
        }

        if (more) {
            int m_a0 = tid >> 2, m_a1 = 64 + (tid >> 2);
            As[nxt][m_a0][akq + 0] = to_tf32(pa0.x);
            As[nxt][m_a0][akq + 1] = to_tf32(pa0.y);
            As[nxt][m_a0][akq + 2] = to_tf32(pa0.z);
            As[nxt][m_a0][akq + 3] = to_tf32(pa0.w);
            As[nxt][m_a1][akq + 0] = to_tf32(pa1.x);
            As[nxt][m_a1][akq + 1] = to_tf32(pa1.y);
            As[nxt][m_a1][akq + 2] = to_tf32(pa1.z);
            As[nxt][m_a1][akq + 3] = to_tf32(pa1.w);
            if (TRANSB) {
                float* bp = &Bs[nxt][bn * BPT + bkq];
                bp[0] = to_tf32(pb.x); bp[1] = to_tf32(pb.y);
                bp[2] = to_tf32(pb.z); bp[3] = to_tf32(pb.w);
            } else {
                float* bp = &Bs[nxt][bkr * BPN + bn4];
                bp[0] = to_tf32(pb.x); bp[1] = to_tf32(pb.y);
                bp[2] = to_tf32(pb.z); bp[3] = to_tf32(pb.w);
            }
            __syncthreads();
        }
    }

    int r0 = m0 + mw + fr;
    int r1 = r0 + 8;
#pragma unroll
    for (int nt = 0; nt < 8; nt++) {
        int cc = n0 + nt * 8 + fc * 2;
        float v00 = acc[nt][0], v01 = acc[nt][1];
        float v10 = acc[nt][2], v11 = acc[nt][3];
        if (HASBIAS) {
            float b0 = bias[cc], b1 = bias[cc + 1];
            v00 += b0; v01 += b1; v10 += b0; v11 += b1;
        }
        if (RELU) {
            v00 = fmaxf(v00, 0.0f); v01 = fmaxf(v01, 0.0f);
            v10 = fmaxf(v10, 0.0f); v11 = fmaxf(v11, 0.0f);
        }
        if (OUTBF16) {
            __nv_bfloat162 h0 = __floats2bfloat162_rn(v00, v01);
            __nv_bfloat162 h1 = __floats2bfloat162_rn(v10, v11);
            *(uint32_t*)&g_qkvh[(size_t)r0 * Nd + cc] = *(uint32_t*)&h0;
            *(uint32_t*)&g_qkvh[(size_t)r1 * Nd + cc] = *(uint32_t*)&h1;
        } else {
            *(float2*)&C[(size_t)r0 * Nd + cc] = make_float2(v00, v01);
            *(float2*)&C[(size_t)r1 * Nd + cc] = make_float2(v10, v11);
        }
    }
}

// ---------------- bf16 tensor-core flash attention ----------------
__device__ __forceinline__ void mma_bf16(float c[4], uint32_t a0, uint32_t a1,
                                         uint32_t a2, uint32_t a3,
                                         uint32_t b0, uint32_t b1) {
    asm volatile(
        "mma.sync.aligned.m16n8k16.row.col.f32.bf16.bf16.f32 "
        "{%0,%1,%2,%3},{%4,%5,%6,%7},{%8,%9},{%0,%1,%2,%3};\n"
        : "+f"(c[0]), "+f"(c[1]), "+f"(c[2]), "+f"(c[3])
        : "r"(a0), "r"(a1), "r"(a2), "r"(a3), "r"(b0), "r"(b1));
}

#define FA_PITCH 72

// writes output into combo buffer: row stride 768, column offset 512
__global__ __launch_bounds__(128) void flash_attn_bf16_kernel() {
    const __nv_bfloat16* __restrict__ qkvh = g_qkvh;
    float* __restrict__ outp = g_scratch + OFF_COMBO + 512;
    const int head = blockIdx.y;
    const int q0 = blockIdx.x * 64;
    const int tid = threadIdx.x;
    const int warp = tid >> 5;
    const int lane = tid & 31;
    const int quad = lane >> 2;
    const int qd = lane & 3;

    __shared__ __align__(16) __nv_bfloat16 Qs[64][FA_PITCH];
    __shared__ __align__(16) __nv_bfloat16 Ks[64][FA_PITCH];
    __shared__ __align__(16) __nv_bfloat16 Vt[64][FA_PITCH];
    __shared__ __align__(16) __nv_bfloat16 Ps[64][FA_PITCH];

#pragma unroll
    for (int ch = 0; ch < 4; ch++) {
        int idx = ch * 128 + tid;
        int r = idx >> 3;
        int c = (idx & 7) * 8;
        *(uint4*)&Qs[r][c] =
            *(const uint4*)&qkvh[(size_t)(q0 + r) * 768 + head * 64 + c];
    }

    float m0r = -1e30f, m1r = -1e30f;
    float l0r = 0.0f, l1r = 0.0f;
    float o[8][4];
#pragma unroll
    for (int nt = 0; nt < 8; nt++)
#pragma unroll
        for (int j = 0; j < 4; j++) o[nt][j] = 0.0f;

    const int qrowA = warp * 16 + quad;
    const int qrowB = qrowA + 8;

    for (int kb = 0; kb < NN / 64; kb++) {
        int kbase = kb * 64;
        __syncthreads();
#pragma unroll
        for (int ch = 0; ch < 4; ch++) {
            int idx = ch * 128 + tid;
            int r = idx >> 3;
            int c = (idx & 7) * 8;
            *(uint4*)&Ks[r][c] =
                *(const uint4*)&qkvh[(size_t)(kbase + r) * 768 + 256 + head * 64 + c];
        }
        {
            int r = tid & 63;
            int d0 = (tid >> 6) * 32;
#pragma unroll
            for (int u = 0; u < 4; u++) {
                uint4 vv = *(const uint4*)&qkvh[(size_t)(kbase + r) * 768 + 512 +
                                                head * 64 + d0 + u * 8];
                __nv_bfloat16 tmp[8];
                *(uint4*)tmp = vv;
#pragma unroll
                for (int j = 0; j < 8; j++) Vt[d0 + u * 8 + j][r] = tmp[j];
            }
        }
        __syncthreads();

        float sc[8][4];
#pragma unroll
        for (int nt = 0; nt < 8; nt++)
#pragma unroll
            for (int j = 0; j < 4; j++) sc[nt][j] = 0.0f;

#pragma unroll
        for (int ks = 0; ks < 4; ks++) {
            int k0 = ks * 16;
            uint32_t a0 = *(const uint32_t*)&Qs[qrowA][k0 + qd * 2];
            uint32_t a1 = *(const uint32_t*)&Qs[qrowB][k0 + qd * 2];
            uint32_t a2 = *(const uint32_t*)&Qs[qrowA][k0 + qd * 2 + 8];
            uint32_t a3 = *(const uint32_t*)&Qs[qrowB][k0 + qd * 2 + 8];
#pragma unroll
            for (int nt = 0; nt < 8; nt++) {
                uint32_t b0 = *(const uint32_t*)&Ks[nt * 8 + quad][k0 + qd * 2];
                uint32_t b1 = *(const uint32_t*)&Ks[nt * 8 + quad][k0 + qd * 2 + 8];
                mma_bf16(sc[nt], a0, a1, a2, a3, b0, b1);
            }
        }

        float mA = -1e30f, mB = -1e30f;
#pragma unroll
        for (int nt = 0; nt < 8; nt++) {
            sc[nt][0] *= 0.125f; sc[nt][1] *= 0.125f;
            sc[nt][2] *= 0.125f; sc[nt][3] *= 0.125f;
            mA = fmaxf(mA, fmaxf(sc[nt][0], sc[nt][1]));
            mB = fmaxf(mB, fmaxf(sc[nt][2], sc[nt][3]));
        }
        mA = fmaxf(mA, __shfl_xor_sync(0xffffffffu, mA, 1));
        mA = fmaxf(mA, __shfl_xor_sync(0xffffffffu, mA, 2));
        mB = fmaxf(mB, __shfl_xor_sync(0xffffffffu, mB, 1));
        mB = fmaxf(mB, __shfl_xor_sync(0xffffffffu, mB, 2));
        float mnA = fmaxf(m0r, mA);
        float mnB = fmaxf(m1r, mB);
        float alA = __expf(m0r - mnA);
        float alB = __expf(m1r - mnB);
        float sumA = 0.0f, sumB = 0.0f;
#pragma unroll
        for (int nt = 0; nt < 8; nt++) {
            float p0 = __expf(sc[nt][0] - mnA);
            float p1 = __expf(sc[nt][1] - mnA);
            float p2 = __expf(sc[nt][2] - mnB);
            float p3 = __expf(sc[nt][3] - mnB);
            sumA += p0 + p1;
            sumB += p2 + p3;
            __nv_bfloat162 hA = __floats2bfloat162_rn(p0, p1);
            __nv_bfloat162 hB = __floats2bfloat162_rn(p2, p3);
            *(uint32_t*)&Ps[qrowA][nt * 8 + qd * 2] = *(uint32_t*)&hA;
            *(uint32_t*)&Ps[qrowB][nt * 8 + qd * 2] = *(uint32_t*)&hB;
        }
        sumA += __shfl_xor_sync(0xffffffffu, sumA, 1);
        sumA += __shfl_xor_sync(0xffffffffu, sumA, 2);
        sumB += __shfl_xor_sync(0xffffffffu, sumB, 1);
        sumB += __shfl_xor_sync(0xffffffffu, sumB, 2);
        l0r = l0r * alA + sumA;
        l1r = l1r * alB + sumB;
        m0r = mnA;
        m1r = mnB;
#pragma unroll
        for (int nt = 0; nt < 8; nt++) {
            o[nt][0] *= alA; o[nt][1] *= alA;
            o[nt][2] *= alB; o[nt][3] *= alB;
        }
        __syncwarp();

#pragma unroll
        for (int ks = 0; ks < 4; ks++) {
            int k0 = ks * 16;
            uint32_t a0 = *(const uint32_t*)&Ps[qrowA][k0 + qd * 2];
            uint32_t a1 = *(const uint32_t*)&Ps[qrowB][k0 + qd * 2];
            uint32_t a2 = *(const uint32_t*)&Ps[qrowA][k0 + qd * 2 + 8];
            uint32_t a3 = *(const uint32_t*)&Ps[qrowB][k0 + qd * 2 + 8];
#pragma unroll
            for (int nt = 0; nt < 8; nt++) {
                uint32_t b0 = *(const uint32_t*)&Vt[nt * 8 + quad][k0 + qd * 2];
                uint32_t b1 = *(const uint32_t*)&Vt[nt * 8 + quad][k0 + qd * 2 + 8];
                mma_bf16(o[nt], a0, a1, a2, a3, b0, b1);
            }
        }
    }

    float invA = 1.0f / l0r;
    float invB = 1.0f / l1r;
    int gA = q0 + qrowA;
    int gB = q0 + qrowB;
#pragma unroll
    for (int nt = 0; nt < 8; nt++) {
        float2 vA = make_float2(o[nt][0] * invA, o[nt][1] * invA);
        float2 vB = make_float2(o[nt][2] * invB, o[nt][3] * invB);
        *(float2*)&outp[(size_t)gA * 768 + head * 64 + nt * 8 + qd * 2] = vA;
        *(float2*)&outp[(size_t)gB * 768 + head * 64 + nt * 8 + qd * 2] = vB;
    }
}

// ---------------- launch (single stream, sequential) ----------------
extern "C" void kernel_launch(void* const* d_in, const int* in_sizes, int n_in,
                              void* d_out, int out_size) {
    const float* x          = (const float*)d_in[0];
    const int*   ei         = (const int*)d_in[1];
    const float* gcn1_w     = (const float*)d_in[2];
    const float* gcn1_b     = (const float*)d_in[3];
    const float* gcn2_w     = (const float*)d_in[4];
    const float* gcn2_b     = (const float*)d_in[5];
    const float* lin_w      = (const float*)d_in[6];
    const float* lin_b      = (const float*)d_in[7];
    const float* in_proj_w  = (const float*)d_in[8];
    const float* in_proj_b  = (const float*)d_in[9];
    const float* out_proj_w = (const float*)d_in[10];
    const float* out_proj_b = (const float*)d_in[11];
    const float* proj_w     = (const float*)d_in[12];
    const float* proj_b     = (const float*)d_in[13];
    float* out = (float*)d_out;

    // CSR build + dinv
    zero_cnt_kernel<<<NN / 256, 256>>>();
    hist_kernel<<<EE / 256, 256>>>(ei);
    scan_kernel<<<1, 1024>>>();
    fill_kernel<<<EE / 256, 256>>>(ei);

    // weight folding
    copy_linw_kernel<<<(HIDDEN * CLASSES / 4) / 256, 256>>>(lin_w);
    wprime_kernel<<<256, 256>>>(out_proj_w, proj_w);
    btot_kernel<<<1, 256>>>(lin_b, out_proj_b, proj_w, proj_b);

    // transformer: qkv (bf16 out) -> flash attention -> combo[:,512:768]
    gemm_tc<true, false, true, true><<<dim3((3 * IN_DIM) / 64, NN / 128), 256>>>(
        x, 0L, in_proj_w, 0L, in_proj_b, 0L, nullptr, 0L, NN, IN_DIM, 3 * IN_DIM);
    flash_attn_bf16_kernel<<<dim3(NN / 64, HEADS), 128>>>();

    // GNN: aggregate-first conv1
    gather_kernel<false><<<dim3(NN / 8, IN_DIM / 128), 256>>>(
        x, 0L, nullptr, OFF_AGGX, IN_DIM, IN_DIM, 0);
    gemm_tc<false, true, true, false><<<dim3(HIDDEN / 64, NN / 128), 256>>>(
        nullptr, OFF_AGGX, gcn1_w, 0L, gcn1_b, 0L, nullptr, OFF_AGG1, NN, IN_DIM, HIDDEN);

    gemm_tc<false, false, false, false><<<dim3(HIDDEN / 64, NN / 128), 256>>>(
        nullptr, OFF_AGG1, gcn2_w, 0L, nullptr, 0L, nullptr, OFF_H2, NN, HIDDEN, HIDDEN);
    gather_kernel<true><<<dim3(NN / 8, HIDDEN / 128), 256>>>(
        nullptr, OFF_H2, gcn2_b, OFF_COMBO, HIDDEN, 768, 0);

    // out = relu([agg2 | attn] @ comboW + b_tot)
    gemm_tc<false, true, true, false><<<dim3(CLASSES / 64, NN / 128), 256>>>(
        nullptr, OFF_COMBO, nullptr, OFF_COMBOW, nullptr, OFF_BTOT, out, 0L, NN, 768, CLASSES);
}

// round 14
// speedup vs baseline: 1.2122x; 1.0078x over previous
#include <cuda_runtime.h>
#include <cuda_bf16.h>
#include <math.h>
#include <stdint.h>

#define NN 4096
#define IN_DIM 256
#define HIDDEN 512
#define CLASSES 256
#define HEADS 4
#define HD 64
#define EE 131072
#define SPLITS 4

// ---------------- scratch ----------------
#define OFF_DINV   0L
#define OFF_AGGX   (OFF_DINV + NN)
#define OFF_AGG1   (OFF_AGGX + (long)NN * IN_DIM)
#define OFF_H2     (OFF_AGG1 + (long)NN * HIDDEN)
#define OFF_COMBO  (OFF_H2   + (long)NN * HIDDEN)
#define OFF_COMBOW (OFF_COMBO + (long)NN * 768)
#define OFF_BTOT   (OFF_COMBOW + 768L * 256)
#define OFF_PARTO  (OFF_BTOT + 256)
#define OFF_PARTML (OFF_PARTO + (long)SPLITS * NN * IN_DIM)
#define SCRATCH_TOTAL (OFF_PARTML + 2L * SPLITS * HEADS * NN)

__device__ __align__(16) float g_scratch[SCRATCH_TOTAL];
__device__ __align__(16) __nv_bfloat16 g_qkvh[(long)NN * 3 * IN_DIM];
__device__ int g_cnt[NN];
__device__ int g_rowptr[NN + 1];
__device__ int g_srcidx[EE];

// ---------------- CSR build ----------------
__global__ void zero_cnt_kernel() {
    int i = blockIdx.x * blockDim.x + threadIdx.x;
    if (i < NN) g_cnt[i] = 0;
}
__global__ void hist_kernel(const int* __restrict__ ei) {
    int i = blockIdx.x * blockDim.x + threadIdx.x;
    if (i < EE) atomicAdd(&g_cnt[ei[EE + i]], 1);
}
__global__ __launch_bounds__(1024) void scan_kernel() {
    __shared__ int sh[1024];
    int t = threadIdx.x;
    int base = t * 4;
    int c0 = g_cnt[base + 0], c1 = g_cnt[base + 1];
    int c2 = g_cnt[base + 2], c3 = g_cnt[base + 3];
    int s = c0 + c1 + c2 + c3;
    sh[t] = s;
    __syncthreads();
    for (int off = 1; off < 1024; off <<= 1) {
        int v = (t >= off) ? sh[t - off] : 0;
        __syncthreads();
        sh[t] += v;
        __syncthreads();
    }
    int run = sh[t] - s;
    g_rowptr[base + 0] = run;            run += c0;
    g_rowptr[base + 1] = run;            run += c1;
    g_rowptr[base + 2] = run;            run += c2;
    g_rowptr[base + 3] = run;            run += c3;
    if (t == 1023) g_rowptr[NN] = run;
    g_scratch[OFF_DINV + base + 0] = rsqrtf((float)c0 + 1.0f);
    g_scratch[OFF_DINV + base + 1] = rsqrtf((float)c1 + 1.0f);
    g_scratch[OFF_DINV + base + 2] = rsqrtf((float)c2 + 1.0f);
    g_scratch[OFF_DINV + base + 3] = rsqrtf((float)c3 + 1.0f);
    g_cnt[base + 0] = 0; g_cnt[base + 1] = 0;
    g_cnt[base + 2] = 0; g_cnt[base + 3] = 0;
}
__global__ void fill_kernel(const int* __restrict__ ei) {
    int e = blockIdx.x * blockDim.x + threadIdx.x;
    if (e >= EE) return;
    int dst = ei[EE + e];
    int pos = g_rowptr[dst] + atomicAdd(&g_cnt[dst], 1);
    g_srcidx[pos] = ei[e];
}

// ---------------- fused GCN aggregation (gather) ----------------
template <bool BIASRELU>
__global__ __launch_bounds__(256) void gather_kernel(const float* __restrict__ hext, long hoff,
                                                     const float* __restrict__ bias,
                                                     long aggoff, int F, int ostride, int coloff) {
    const float* __restrict__ h = hext ? hext : (const float*)(g_scratch + hoff);
    float* __restrict__ agg = g_scratch + aggoff;
    const float* __restrict__ dinv = g_scratch + OFF_DINV;
    const int warp = threadIdx.x >> 5;
    const int lane = threadIdx.x & 31;
    const int node = blockIdx.x * 8 + warp;
    const int c = blockIdx.y * 128 + lane * 4;

    float dd = dinv[node];
    float4 hv = *(const float4*)&h[(size_t)node * F + c];
    float sw = dd * dd;
    float4 acc = make_float4(hv.x * sw, hv.y * sw, hv.z * sw, hv.w * sw);
    if (BIASRELU) {
        float4 b4 = *(const float4*)&bias[c];
        acc.x += b4.x; acc.y += b4.y; acc.z += b4.z; acc.w += b4.w;
    }

    int beg = g_rowptr[node];
    int end = g_rowptr[node + 1];
    int j = beg;
    for (; j + 2 <= end; j += 2) {
        int s0 = g_srcidx[j];
        int s1 = g_srcidx[j + 1];
        float w0 = dinv[s0] * dd;
        float w1 = dinv[s1] * dd;
        float4 v0 = *(const float4*)&h[(size_t)s0 * F + c];
        float4 v1 = *(const float4*)&h[(size_t)s1 * F + c];
        acc.x += v0.x * w0 + v1.x * w1;
        acc.y += v0.y * w0 + v1.y * w1;
        acc.z += v0.z * w0 + v1.z * w1;
        acc.w += v0.w * w0 + v1.w * w1;
    }
    if (j < end) {
        int s0 = g_srcidx[j];
        float w0 = dinv[s0] * dd;
        float4 v0 = *(const float4*)&h[(size_t)s0 * F + c];
        acc.x += v0.x * w0; acc.y += v0.y * w0;
        acc.z += v0.z * w0; acc.w += v0.w * w0;
    }
    if (BIASRELU) {
        acc.x = fmaxf(acc.x, 0.0f); acc.y = fmaxf(acc.y, 0.0f);
        acc.z = fmaxf(acc.z, 0.0f); acc.w = fmaxf(acc.w, 0.0f);
    }
    *(float4*)&agg[(size_t)node * ostride + coloff + c] = acc;
}

// ---------------- epilogue-fold prep kernels ----------------
__global__ void copy_linw_kernel(const float* __restrict__ lin_w) {
    int i = blockIdx.x * blockDim.x + threadIdx.x;
    float4 v = *(const float4*)&lin_w[4L * i];
    *(float4*)&g_scratch[OFF_COMBOW + 4L * i] = v;
}
__global__ __launch_bounds__(256) void wprime_kernel(const float* __restrict__ out_w,
                                                     const float* __restrict__ proj_w) {
    int i = blockIdx.x;
    int j = threadIdx.x;
    float acc = 0.0f;
#pragma unroll 4
    for (int k = 0; k < 256; k++)
        acc += __ldg(&out_w[k * 256 + i]) * proj_w[k * 256 + j];
    g_scratch[OFF_COMBOW + (512L + i) * 256 + j] = acc;
}
__global__ __launch_bounds__(256) void btot_kernel(const float* __restrict__ lin_b,
                                                   const float* __restrict__ out_b,
                                                   const float* __restrict__ proj_w,
                                                   const float* __restrict__ proj_b) {
    int j = threadIdx.x;
    float acc = lin_b[j] + proj_b[j];
#pragma unroll 4
    for (int k = 0; k < 256; k++)
        acc += __ldg(&out_b[k]) * proj_w[k * 256 + j];
    g_scratch[OFF_BTOT + j] = acc;
}

// ---------------- tf32 helpers ----------------
__device__ __forceinline__ float to_tf32(float x) {
    float r;
    asm("cvt.rna.tf32.f32 %0, %1;" : "=f"(r) : "f"(x));
    return r;
}
__device__ __forceinline__ void mma_tf32(float c[4], float a0, float a1, float a2,
                                         float a3, float b0, float b1) {
    uint32_t ua0 = __float_as_uint(a0), ua1 = __float_as_uint(a1);
    uint32_t ua2 = __float_as_uint(a2), ua3 = __float_as_uint(a3);
    uint32_t ub0 = __float_as_uint(b0), ub1 = __float_as_uint(b1);
    asm volatile(
        "mma.sync.aligned.m16n8k8.row.col.f32.tf32.tf32.f32 "
        "{%0,%1,%2,%3},{%4,%5,%6,%7},{%8,%9},{%0,%1,%2,%3};\n"
        : "+f"(c[0]), "+f"(c[1]), "+f"(c[2]), "+f"(c[3])
        : "r"(ua0), "r"(ua1), "r"(ua2), "r"(ua3), "r"(ub0), "r"(ub1));
}

// ---------------- tf32 tensor-core GEMM, double buffered ----------------
#define AP 20
#define BPN 72
#define BPT 20
template <bool TRANSB, bool RELU, bool HASBIAS, bool OUTBF16>
__global__ __launch_bounds__(256) void gemm_tc(const float* __restrict__ Aext, long aoff,
                                               const float* __restrict__ Bext, long boff,
                                               const float* __restrict__ biasext, long biasoff,
                                               float* __restrict__ Cext, long coff,
                                               int M, int K, int Nd) {
    const float* __restrict__ A = Aext ? Aext : (const float*)(g_scratch + aoff);
    const float* __restrict__ B = Bext ? Bext : (const float*)(g_scratch + boff);
    const float* __restrict__ bias = HASBIAS ? (biasext ? biasext : (const float*)(g_scratch + biasoff)) : nullptr;
    float* __restrict__ C = Cext ? Cext : (g_scratch + coff);

    constexpr int BSZ = TRANSB ? 64 * BPT : 16 * BPN;
    __shared__ float As[2][128][AP];
    __shared__ float Bs[2][BSZ];

    const int tid = threadIdx.x;
    const int warp = tid >> 5, lane = tid & 31;
    const int fr = lane >> 2, fc = lane & 3;
    const int mw = warp * 16;
    const int m0 = blockIdx.y * 128, n0 = blockIdx.x * 64;

    const int akq = (tid & 3) * 4;
    const int bn = tid >> 2;
    const int bkq = (tid & 3) * 4;
    const int bkr = tid >> 4;
    const int bn4 = (tid & 15) * 4;

    float4 pa0, pa1, pb;
    {
        int m_a0 = tid >> 2, m_a1 = 64 + (tid >> 2);
        pa0 = *(const float4*)(A + (size_t)(m0 + m_a0) * K + akq);
        pa1 = *(const float4*)(A + (size_t)(m0 + m_a1) * K + akq);
        if (TRANSB)
            pb = *(const float4*)(B + (size_t)(n0 + bn) * K + bkq);
        else
            pb = *(const float4*)(B + (size_t)bkr * Nd + n0 + bn4);
    }

    float acc[8][4];
#pragma unroll
    for (int nt = 0; nt < 8; nt++)
#pragma unroll
        for (int j = 0; j < 4; j++) acc[nt][j] = 0.0f;

    const int nk = K >> 4;
    {
        int m_a0 = tid >> 2, m_a1 = 64 + (tid >> 2);
        As[0][m_a0][akq + 0] = to_tf32(pa0.x);
        As[0][m_a0][akq + 1] = to_tf32(pa0.y);
        As[0][m_a0][akq + 2] = to_tf32(pa0.z);
        As[0][m_a0][akq + 3] = to_tf32(pa0.w);
        As[0][m_a1][akq + 0] = to_tf32(pa1.x);
        As[0][m_a1][akq + 1] = to_tf32(pa1.y);
        As[0][m_a1][akq + 2] = to_tf32(pa1.z);
        As[0][m_a1][akq + 3] = to_tf32(pa1.w);
        if (TRANSB) {
            float* bp = &Bs[0][bn * BPT + bkq];
            bp[0] = to_tf32(pb.x); bp[1] = to_tf32(pb.y);
            bp[2] = to_tf32(pb.z); bp[3] = to_tf32(pb.w);
        } else {
            float* bp = &Bs[0][bkr * BPN + bn4];
            bp[0] = to_tf32(pb.x); bp[1] = to_tf32(pb.y);
            bp[2] = to_tf32(pb.z); bp[3] = to_tf32(pb.w);
        }
    }
    __syncthreads();

    for (int k0i = 0; k0i < nk; k0i++) {
        const int cur = k0i & 1, nxt = cur ^ 1;
        const bool more = (k0i + 1) < nk;
        if (more) {
            int k0 = (k0i + 1) << 4;
            int m_a0 = tid >> 2, m_a1 = 64 + (tid >> 2);
            pa0 = *(const float4*)(A + (size_t)(m0 + m_a0) * K + k0 + akq);
            pa1 = *(const float4*)(A + (size_t)(m0 + m_a1) * K + k0 + akq);
            if (TRANSB)
                pb = *(const float4*)(B + (size_t)(n0 + bn) * K + k0 + bkq);
            else
                pb = *(const float4*)(B + (size_t)(k0 + bkr) * Nd + n0 + bn4);
        }

#pragma unroll
        for (int ks = 0; ks < 2; ks++) {
            int kk = ks * 8;
            float a0 = As[cur][mw + fr][kk + fc];
            float a1 = As[cur][mw + fr + 8][kk + fc];
            float a2 = As[cur][mw + fr][kk + fc + 4];
            float a3 = As[cur][mw + fr + 8][kk + fc + 4];
#pragma unroll
            for (int nt = 0; nt < 8; nt++) {
                float b0, b1;
                if (TRANSB) {
                    b0 = Bs[cur][(nt * 8 + fr) * BPT + kk + fc];
                    b1 = Bs[cur][(nt * 8 + fr) * BPT + kk + fc + 4];
                } else {
                    b0 = Bs[cur][(kk + fc) * BPN + nt * 8 + fr];
                    b1 = Bs[cur][(kk + fc + 4) * BPN + nt * 8 + fr];
                }
                mma_tf32(acc[nt], a0, a1, a2, a3, b0, b1);
            }
        }

        if (more) {
            int m_a0 = tid >> 2, m_a1 = 64 + (tid >> 2);
            As[nxt][m_a0][akq + 0] = to_tf32(pa0.x);
            As[nxt][m_a0][akq + 1] = to_tf32(pa0.y);
            As[nxt][m_a0][akq + 2] = to_tf32(pa0.z);
            As[nxt][m_a0][akq + 3] = to_tf32(pa0.w);
            As[nxt][m_a1][akq + 0] = to_tf32(pa1.x);
            As[nxt][m_a1][akq + 1] = to_tf32(pa1.y);
            As[nxt][m_a1][akq + 2] = to_tf32(pa1.z);
            As[nxt][m_a1][akq + 3] = to_tf32(pa1.w);
            if (TRANSB) {
                float* bp = &Bs[nxt][bn * BPT + bkq];
                bp[0] = to_tf32(pb.x); bp[1] = to_tf32(pb.y);
                bp[2] = to_tf32(pb.z); bp[3] = to_tf32(pb.w);
            } else {
                float* bp = &Bs[nxt][bkr * BPN + bn4];
                bp[0] = to_tf32(pb.x); bp[1] = to_tf32(pb.y);
                bp[2] = to_tf32(pb.z); bp[3] = to_tf32(pb.w);
            }
            __syncthreads();
        }
    }

    int r0 = m0 + mw + fr;
    int r1 = r0 + 8;
#pragma unroll
    for (int nt = 0; nt < 8; nt++) {
        int cc = n0 + nt * 8 + fc * 2;
        float v00 = acc[nt][0], v01 = acc[nt][1];
        float v10 = acc[nt][2], v11 = acc[nt][3];
        if (HASBIAS) {
            float b0 = bias[cc], b1 = bias[cc + 1];
            v00 += b0; v01 += b1; v10 += b0; v11 += b1;
        }
        if (RELU) {
            v00 = fmaxf(v00, 0.0f); v01 = fmaxf(v01, 0.0f);
            v10 = fmaxf(v10, 0.0f); v11 = fmaxf(v11, 0.0f);
        }
        if (OUTBF16) {
            __nv_bfloat162 h0 = __floats2bfloat162_rn(v00, v01);
            __nv_bfloat162 h1 = __floats2bfloat162_rn(v10, v11);
            *(uint32_t*)&g_qkvh[(size_t)r0 * Nd + cc] = *(uint32_t*)&h0;
            *(uint32_t*)&g_qkvh[(size_t)r1 * Nd + cc] = *(uint32_t*)&h1;
        } else {
            *(float2*)&C[(size_t)r0 * Nd + cc] = make_float2(v00, v01);
            *(float2*)&C[(size_t)r1 * Nd + cc] = make_float2(v10, v11);
        }
    }
}

// ---------------- bf16 tensor-core flash attention (split-K) ----------------
__device__ __forceinline__ void mma_bf16(float c[4], uint32_t a0, uint32_t a1,
                                         uint32_t a2, uint32_t a3,
                                         uint32_t b0, uint32_t b1) {
    asm volatile(
        "mma.sync.aligned.m16n8k16.row.col.f32.bf16.bf16.f32 "
        "{%0,%1,%2,%3},{%4,%5,%6,%7},{%8,%9},{%0,%1,%2,%3};\n"
        : "+f"(c[0]), "+f"(c[1]), "+f"(c[2]), "+f"(c[3])
        : "r"(a0), "r"(a1), "r"(a2), "r"(a3), "r"(b0), "r"(b1));
}

#define FA_PITCH 72
#define KB_PER_SPLIT (NN / 64 / SPLITS)  // 16

// grid (NN/64, HEADS, SPLITS). Emits unnormalized partial O + (m,l).
__global__ __launch_bounds__(128) void flash_attn_split_kernel() {
    const __nv_bfloat16* __restrict__ qkvh = g_qkvh;
    const int head = blockIdx.y;
    const int split = blockIdx.z;
    const int q0 = blockIdx.x * 64;
    const int tid = threadIdx.x;
    const int warp = tid >> 5;
    const int lane = tid & 31;
    const int quad = lane >> 2;
    const int qd = lane & 3;

    __shared__ __align__(16) __nv_bfloat16 Qs[64][FA_PITCH];
    __shared__ __align__(16) __nv_bfloat16 Ks[64][FA_PITCH];
    __shared__ __align__(16) __nv_bfloat16 Vt[64][FA_PITCH];
    __shared__ __align__(16) __nv_bfloat16 Ps[64][FA_PITCH];

#pragma unroll
    for (int ch = 0; ch < 4; ch++) {
        int idx = ch * 128 + tid;
        int r = idx >> 3;
        int c = (idx & 7) * 8;
        *(uint4*)&Qs[r][c] =
            *(const uint4*)&qkvh[(size_t)(q0 + r) * 768 + head * 64 + c];
    }

    float m0r = -1e30f, m1r = -1e30f;
    float l0r = 0.0f, l1r = 0.0f;
    float o[8][4];
#pragma unroll
    for (int nt = 0; nt < 8; nt++)
#pragma unroll
        for (int j = 0; j < 4; j++) o[nt][j] = 0.0f;

    const int qrowA = warp * 16 + quad;
    const int qrowB = qrowA + 8;

    const int kb_beg = split * KB_PER_SPLIT;
    for (int kb = kb_beg; kb < kb_beg + KB_PER_SPLIT; kb++) {
        int kbase = kb * 64;
        __syncthreads();
#pragma unroll
        for (int ch = 0; ch < 4; ch++) {
            int idx = ch * 128 + tid;
            int r = idx >> 3;
            int c = (idx & 7) * 8;
            *(uint4*)&Ks[r][c] =
                *(const uint4*)&qkvh[(size_t)(kbase + r) * 768 + 256 + head * 64 + c];
        }
        {
            int r = tid & 63;
            int d0 = (tid >> 6) * 32;
#pragma unroll
            for (int u = 0; u < 4; u++) {
                uint4 vv = *(const uint4*)&qkvh[(size_t)(kbase + r) * 768 + 512 +
                                                head * 64 + d0 + u * 8];
                __nv_bfloat16 tmp[8];
                *(uint4*)tmp = vv;
#pragma unroll
                for (int j = 0; j < 8; j++) Vt[d0 + u * 8 + j][r] = tmp[j];
            }
        }
        __syncthreads();

        float sc[8][4];
#pragma unroll
        for (int nt = 0; nt < 8; nt++)
#pragma unroll
            for (int j = 0; j < 4; j++) sc[nt][j] = 0.0f;

#pragma unroll
        for (int ks = 0; ks < 4; ks++) {
            int k0 = ks * 16;
            uint32_t a0 = *(const uint32_t*)&Qs[qrowA][k0 + qd * 2];
            uint32_t a1 = *(const uint32_t*)&Qs[qrowB][k0 + qd * 2];
            uint32_t a2 = *(const uint32_t*)&Qs[qrowA][k0 + qd * 2 + 8];
            uint32_t a3 = *(const uint32_t*)&Qs[qrowB][k0 + qd * 2 + 8];
#pragma unroll
            for (int nt = 0; nt < 8; nt++) {
                uint32_t b0 = *(const uint32_t*)&Ks[nt * 8 + quad][k0 + qd * 2];
                uint32_t b1 = *(const uint32_t*)&Ks[nt * 8 + quad][k0 + qd * 2 + 8];
                mma_bf16(sc[nt], a0, a1, a2, a3, b0, b1);
            }
        }

        float mA = -1e30f, mB = -1e30f;
#pragma unroll
        for (int nt = 0; nt < 8; nt++) {
            sc[nt][0] *= 0.125f; sc[nt][1] *= 0.125f;
            sc[nt][2] *= 0.125f; sc[nt][3] *= 0.125f;
            mA = fmaxf(mA, fmaxf(sc[nt][0], sc[nt][1]));
            mB = fmaxf(mB, fmaxf(sc[nt][2], sc[nt][3]));
        }
        mA = fmaxf(mA, __shfl_xor_sync(0xffffffffu, mA, 1));
        mA = fmaxf(mA, __shfl_xor_sync(0xffffffffu, mA, 2));
        mB = fmaxf(mB, __shfl_xor_sync(0xffffffffu, mB, 1));
        mB = fmaxf(mB, __shfl_xor_sync(0xffffffffu, mB, 2));
        float mnA = fmaxf(m0r, mA);
        float mnB = fmaxf(m1r, mB);
        float alA = __expf(m0r - mnA);
        float alB = __expf(m1r - mnB);
        float sumA = 0.0f, sumB = 0.0f;
#pragma unroll
        for (int nt = 0; nt < 8; nt++) {
            float p0 = __expf(sc[nt][0] - mnA);
            float p1 = __expf(sc[nt][1] - mnA);
            float p2 = __expf(sc[nt][2] - mnB);
            float p3 = __expf(sc[nt][3] - mnB);
            sumA += p0 + p1;
            sumB += p2 + p3;
            __nv_bfloat162 hA = __floats2bfloat162_rn(p0, p1);
            __nv_bfloat162 hB = __floats2bfloat162_rn(p2, p3);
            *(uint32_t*)&Ps[qrowA][nt * 8 + qd * 2] = *(uint32_t*)&hA;
            *(uint32_t*)&Ps[qrowB][nt * 8 + qd * 2] = *(uint32_t*)&hB;
        }
        sumA += __shfl_xor_sync(0xffffffffu, sumA, 1);
        sumA += __shfl_xor_sync(0xffffffffu, sumA, 2);
        sumB += __shfl_xor_sync(0xffffffffu, sumB, 1);
        sumB += __shfl_xor_sync(0xffffffffu, sumB, 2);
        l0r = l0r * alA + sumA;
        l1r = l1r * alB + sumB;
        m0r = mnA;
        m1r = mnB;
#pragma unroll
        for (int nt = 0; nt < 8; nt++) {
            o[nt][0] *= alA; o[nt][1] *= alA;
            o[nt][2] *= alB; o[nt][3] *= alB;
        }
        __syncwarp();

#pragma unroll
        for (int ks = 0; ks < 4; ks++) {
            int k0 = ks * 16;
            uint32_t a0 = *(const uint32_t*)&Ps[qrowA][k0 + qd * 2];
            uint32_t a1 = *(const uint32_t*)&Ps[qrowB][k0 + qd * 2];
            uint32_t a2 = *(const uint32_t*)&Ps[qrowA][k0 + qd * 2 + 8];
            uint32_t a3 = *(const uint32_t*)&Ps[qrowB][k0 + qd * 2 + 8];
#pragma unroll
            for (int nt = 0; nt < 8; nt++) {
                uint32_t b0 = *(const uint32_t*)&Vt[nt * 8 + quad][k0 + qd * 2];
                uint32_t b1 = *(const uint32_t*)&Vt[nt * 8 + quad][k0 + qd * 2 + 8];
                mma_bf16(o[nt], a0, a1, a2, a3, b0, b1);
            }
        }
    }

    // partial epilogue: unnormalized o + (m, l)
    float* __restrict__ po = g_scratch + OFF_PARTO + (long)split * NN * IN_DIM;
    int gA = q0 + qrowA;
    int gB = q0 + qrowB;
#pragma unroll
    for (int nt = 0; nt < 8; nt++) {
        *(float2*)&po[(size_t)gA * IN_DIM + head * 64 + nt * 8 + qd * 2] =
            make_float2(o[nt][0], o[nt][1]);
        *(float2*)&po[(size_t)gB * IN_DIM + head * 64 + nt * 8 + qd * 2] =
            make_float2(o[nt][2], o[nt][3]);
    }
    if (qd == 0) {
        long mlbase = OFF_PARTML + ((long)split * HEADS + head) * NN;
        long lbase = mlbase + (long)SPLITS * HEADS * NN;
        g_scratch[mlbase + gA] = m0r;
        g_scratch[mlbase + gB] = m1r;
        g_scratch[lbase + gA] = l0r;
        g_scratch[lbase + gB] = l1r;
    }
}

// combine partial softmax results -> combo[:, 512:768]
// one thread per (row, head, 4-wide d chunk): NN*HEADS*16 threads
__global__ __launch_bounds__(256) void attn_combine_kernel() {
    int idx = blockIdx.x * 256 + threadIdx.x;
    int dq = idx & 15;
    int h = (idx >> 4) & (HEADS - 1);
    int row = idx >> 6;

    float m[SPLITS], l[SPLITS];
    float M = -1e30f;
#pragma unroll
    for (int s = 0; s < SPLITS; s++) {
        long mlbase = OFF_PARTML + ((long)s * HEADS + h) * NN;
        m[s] = g_scratch[mlbase + row];
        l[s] = g_scratch[mlbase + (long)SPLITS * HEADS * NN + row];
        M = fmaxf(M, m[s]);
    }
    float L = 0.0f;
    float4 acc = make_float4(0.0f, 0.0f, 0.0f, 0.0f);
#pragma unroll
    for (int s = 0; s < SPLITS; s++) {
        float w = __expf(m[s] - M);
        L += l[s] * w;
        const float* po = g_scratch + OFF_PARTO + (long)s * NN * IN_DIM;
        float4 v = *(const float4*)&po[(size_t)row * IN_DIM + h * 64 + dq * 4];
        acc.x += v.x * w; acc.y += v.y * w;
        acc.z += v.z * w; acc.w += v.w * w;
    }
    float inv = 1.0f / L;
    acc.x *= inv; acc.y *= inv; acc.z *= inv; acc.w *= inv;
    *(float4*)&g_scratch[OFF_COMBO + (size_t)row * 768 + 512 + h * 64 + dq * 4] = acc;
}

// ---------------- launch (single stream, sequential) ----------------
extern "C" void kernel_launch(void* const* d_in, const int* in_sizes, int n_in,
                              void* d_out, int out_size) {
    const float* x          = (const float*)d_in[0];
    const int*   ei         = (const int*)d_in[1];
    const float* gcn1_w     = (const float*)d_in[2];
    const float* gcn1_b     = (const float*)d_in[3];
    const float* gcn2_w     = (const float*)d_in[4];
    const float* gcn2_b     = (const float*)d_in[5];
    const float* lin_w      = (const float*)d_in[6];
    const float* lin_b      = (const float*)d_in[7];
    const float* in_proj_w  = (const float*)d_in[8];
    const float* in_proj_b  = (const float*)d_in[9];
    const float* out_proj_w = (const float*)d_in[10];
    const float* out_proj_b = (const float*)d_in[11];
    const float* proj_w     = (const float*)d_in[12];
    const float* proj_b     = (const float*)d_in[13];
    float* out = (float*)d_out;

    // CSR build + dinv
    zero_cnt_kernel<<<NN / 256, 256>>>();
    hist_kernel<<<EE / 256, 256>>>(ei);
    scan_kernel<<<1, 1024>>>();
    fill_kernel<<<EE / 256, 256>>>(ei);

    // weight folding
    copy_linw_kernel<<<(HIDDEN * CLASSES / 4) / 256, 256>>>(lin_w);
    wprime_kernel<<<256, 256>>>(out_proj_w, proj_w);
    btot_kernel<<<1, 256>>>(lin_b, out_proj_b, proj_w, proj_b);

    // transformer: qkv (bf16 out) -> split-K flash attention -> combine
    gemm_tc<true, false, true, true><<<dim3((3 * IN_DIM) / 64, NN / 128), 256>>>(
        x, 0L, in_proj_w, 0L, in_proj_b, 0L, nullptr, 0L, NN, IN_DIM, 3 * IN_DIM);
    flash_attn_split_kernel<<<dim3(NN / 64, HEADS, SPLITS), 128>>>();
    attn_combine_kernel<<<(NN * HEADS * 16) / 256, 256>>>();

    // GNN: aggregate-first conv1
    gather_kernel<false><<<dim3(NN / 8, IN_DIM / 128), 256>>>(
        x, 0L, nullptr, OFF_AGGX, IN_DIM, IN_DIM, 0);
    gemm_tc<false, true, true, false><<<dim3(HIDDEN / 64, NN / 128), 256>>>(
        nullptr, OFF_AGGX, gcn1_w, 0L, gcn1_b, 0L, nullptr, OFF_AGG1, NN, IN_DIM, HIDDEN);

    gemm_tc<false, false, false, false><<<dim3(HIDDEN / 64, NN / 128), 256>>>(
        nullptr, OFF_AGG1, gcn2_w, 0L, nullptr, 0L, nullptr, OFF_H2, NN, HIDDEN, HIDDEN);
    gather_kernel<true><<<dim3(NN / 8, HIDDEN / 128), 256>>>(
        nullptr, OFF_H2, gcn2_b, OFF_COMBO, HIDDEN, 768, 0);

    // out = relu([agg2 | attn] @ comboW + b_tot)
    gemm_tc<false, true, true, false><<<dim3(CLASSES / 64, NN / 128), 256>>>(
        nullptr, OFF_COMBO, nullptr, OFF_COMBOW, nullptr, OFF_BTOT, out, 0L, NN, 768, CLASSES);
}

// round 15
// speedup vs baseline: 1.2201x; 1.0065x over previous
#include <cuda_runtime.h>
#include <cuda_bf16.h>
#include <math.h>
#include <stdint.h>

#define NN 4096
#define IN_DIM 256
#define HIDDEN 512
#define CLASSES 256
#define HEADS 4
#define HD 64
#define EE 131072
#define SPLITS 4

// ---------------- scratch ----------------
#define OFF_DINV   0L
#define OFF_AGGX   (OFF_DINV + NN)
#define OFF_AGG1   (OFF_AGGX + (long)NN * IN_DIM)
#define OFF_H2     (OFF_AGG1 + (long)NN * HIDDEN)
#define OFF_COMBO  (OFF_H2   + (long)NN * HIDDEN)
#define OFF_COMBOW (OFF_COMBO + (long)NN * 768)
#define OFF_BTOT   (OFF_COMBOW + 768L * 256)
#define OFF_PARTO  (OFF_BTOT + 256)
#define OFF_PARTML (OFF_PARTO + (long)SPLITS * NN * IN_DIM)
#define SCRATCH_TOTAL (OFF_PARTML + 2L * SPLITS * HEADS * NN)

__device__ __align__(16) float g_scratch[SCRATCH_TOTAL];
__device__ __align__(16) __nv_bfloat16 g_qkvh[(long)NN * 3 * IN_DIM];
__device__ int g_cnt[NN];         // zero-init; returns to 0 after each full pass
__device__ int g_rowptr[NN + 1];
__device__ int g_srcidx[EE];

// ---------------- CSR build ----------------
__global__ void hist_kernel(const int* __restrict__ ei) {
    int i = blockIdx.x * blockDim.x + threadIdx.x;
    if (i < EE) atomicAdd(&g_cnt[ei[EE + i]], 1);
}
// scan leaves cnt = deg (fill consumes it back to 0)
__global__ __launch_bounds__(1024) void scan_kernel() {
    __shared__ int sh[1024];
    int t = threadIdx.x;
    int base = t * 4;
    int c0 = g_cnt[base + 0], c1 = g_cnt[base + 1];
    int c2 = g_cnt[base + 2], c3 = g_cnt[base + 3];
    int s = c0 + c1 + c2 + c3;
    sh[t] = s;
    __syncthreads();
    for (int off = 1; off < 1024; off <<= 1) {
        int v = (t >= off) ? sh[t - off] : 0;
        __syncthreads();
        sh[t] += v;
        __syncthreads();
    }
    int run = sh[t] - s;
    g_rowptr[base + 0] = run;            run += c0;
    g_rowptr[base + 1] = run;            run += c1;
    g_rowptr[base + 2] = run;            run += c2;
    g_rowptr[base + 3] = run;            run += c3;
    if (t == 1023) g_rowptr[NN] = run;
    g_scratch[OFF_DINV + base + 0] = rsqrtf((float)c0 + 1.0f);
    g_scratch[OFF_DINV + base + 1] = rsqrtf((float)c1 + 1.0f);
    g_scratch[OFF_DINV + base + 2] = rsqrtf((float)c2 + 1.0f);
    g_scratch[OFF_DINV + base + 3] = rsqrtf((float)c3 + 1.0f);
}
// consumes cnt back to 0 (atomicSub): slot = rowptr + old-1
__global__ void fill_kernel(const int* __restrict__ ei) {
    int e = blockIdx.x * blockDim.x + threadIdx.x;
    if (e >= EE) return;
    int dst = ei[EE + e];
    int pos = g_rowptr[dst] + atomicSub(&g_cnt[dst], 1) - 1;
    g_srcidx[pos] = ei[e];
}

// ---------------- fused GCN aggregation (gather) ----------------
template <bool BIASRELU>
__global__ __launch_bounds__(256) void gather_kernel(const float* __restrict__ hext, long hoff,
                                                     const float* __restrict__ bias,
                                                     long aggoff, int F, int ostride, int coloff) {
    const float* __restrict__ h = hext ? hext : (const float*)(g_scratch + hoff);
    float* __restrict__ agg = g_scratch + aggoff;
    const float* __restrict__ dinv = g_scratch + OFF_DINV;
    const int warp = threadIdx.x >> 5;
    const int lane = threadIdx.x & 31;
    const int node = blockIdx.x * 8 + warp;
    const int c = blockIdx.y * 128 + lane * 4;

    float dd = dinv[node];
    float4 hv = *(const float4*)&h[(size_t)node * F + c];
    float sw = dd * dd;
    float4 acc = make_float4(hv.x * sw, hv.y * sw, hv.z * sw, hv.w * sw);
    if (BIASRELU) {
        float4 b4 = *(const float4*)&bias[c];
        acc.x += b4.x; acc.y += b4.y; acc.z += b4.z; acc.w += b4.w;
    }

    int beg = g_rowptr[node];
    int end = g_rowptr[node + 1];
    int j = beg;
    for (; j + 4 <= end; j += 4) {
        int s0 = g_srcidx[j], s1 = g_srcidx[j + 1];
        int s2 = g_srcidx[j + 2], s3 = g_srcidx[j + 3];
        float w0 = dinv[s0] * dd, w1 = dinv[s1] * dd;
        float w2 = dinv[s2] * dd, w3 = dinv[s3] * dd;
        float4 v0 = *(const float4*)&h[(size_t)s0 * F + c];
        float4 v1 = *(const float4*)&h[(size_t)s1 * F + c];
        float4 v2 = *(const float4*)&h[(size_t)s2 * F + c];
        float4 v3 = *(const float4*)&h[(size_t)s3 * F + c];
        acc.x += v0.x * w0 + v1.x * w1 + v2.x * w2 + v3.x * w3;
        acc.y += v0.y * w0 + v1.y * w1 + v2.y * w2 + v3.y * w3;
        acc.z += v0.z * w0 + v1.z * w1 + v2.z * w2 + v3.z * w3;
        acc.w += v0.w * w0 + v1.w * w1 + v2.w * w2 + v3.w * w3;
    }
    for (; j < end; j++) {
        int s0 = g_srcidx[j];
        float w0 = dinv[s0] * dd;
        float4 v0 = *(const float4*)&h[(size_t)s0 * F + c];
        acc.x += v0.x * w0; acc.y += v0.y * w0;
        acc.z += v0.z * w0; acc.w += v0.w * w0;
    }
    if (BIASRELU) {
        acc.x = fmaxf(acc.x, 0.0f); acc.y = fmaxf(acc.y, 0.0f);
        acc.z = fmaxf(acc.z, 0.0f); acc.w = fmaxf(acc.w, 0.0f);
    }
    *(float4*)&agg[(size_t)node * ostride + coloff + c] = acc;
}

// ---------------- epilogue-fold prep kernels ----------------
__global__ void copy_linw_kernel(const float* __restrict__ lin_w) {
    int i = blockIdx.x * blockDim.x + threadIdx.x;
    float4 v = *(const float4*)&lin_w[4L * i];
    *(float4*)&g_scratch[OFF_COMBOW + 4L * i] = v;
}
__global__ __launch_bounds__(256) void wprime_kernel(const float* __restrict__ out_w,
                                                     const float* __restrict__ proj_w) {
    int i = blockIdx.x;
    int j = threadIdx.x;
    float acc = 0.0f;
#pragma unroll 4
    for (int k = 0; k < 256; k++)
        acc += __ldg(&out_w[k * 256 + i]) * proj_w[k * 256 + j];
    g_scratch[OFF_COMBOW + (512L + i) * 256 + j] = acc;
}
__global__ __launch_bounds__(256) void btot_kernel(const float* __restrict__ lin_b,
                                                   const float* __restrict__ out_b,
                                                   const float* __restrict__ proj_w,
                                                   const float* __restrict__ proj_b) {
    int j = threadIdx.x;
    float acc = lin_b[j] + proj_b[j];
#pragma unroll 4
    for (int k = 0; k < 256; k++)
        acc += __ldg(&out_b[k]) * proj_w[k * 256 + j];
    g_scratch[OFF_BTOT + j] = acc;
}

// ---------------- tf32 helpers ----------------
__device__ __forceinline__ float to_tf32(float x) {
    float r;
    asm("cvt.rna.tf32.f32 %0, %1;" : "=f"(r) : "f"(x));
    return r;
}
__device__ __forceinline__ void mma_tf32(float c[4], float a0, float a1, float a2,
                                         float a3, float b0, float b1) {
    uint32_t ua0 = __float_as_uint(a0), ua1 = __float_as_uint(a1);
    uint32_t ua2 = __float_as_uint(a2), ua3 = __float_as_uint(a3);
    uint32_t ub0 = __float_as_uint(b0), ub1 = __float_as_uint(b1);
    asm volatile(
        "mma.sync.aligned.m16n8k8.row.col.f32.tf32.tf32.f32 "
        "{%0,%1,%2,%3},{%4,%5,%6,%7},{%8,%9},{%0,%1,%2,%3};\n"
        : "+f"(c[0]), "+f"(c[1]), "+f"(c[2]), "+f"(c[3])
        : "r"(ua0), "r"(ua1), "r"(ua2), "r"(ua3), "r"(ub0), "r"(ub1));
}

// ---------------- tf32 tensor-core GEMM: BM=128 BN=128 BK=16, 8 warps 4x2 ----
#define AP 20
#define BPN 132
#define BPT 20
template <bool TRANSB, bool RELU, bool HASBIAS, bool OUTBF16>
__global__ __launch_bounds__(256) void gemm_tc(const float* __restrict__ Aext, long aoff,
                                               const float* __restrict__ Bext, long boff,
                                               const float* __restrict__ biasext, long biasoff,
                                               float* __restrict__ Cext, long coff,
                                               int M, int K, int Nd) {
    const float* __restrict__ A = Aext ? Aext : (const float*)(g_scratch + aoff);
    const float* __restrict__ B = Bext ? Bext : (const float*)(g_scratch + boff);
    const float* __restrict__ bias = HASBIAS ? (biasext ? biasext : (const float*)(g_scratch + biasoff)) : nullptr;
    float* __restrict__ C = Cext ? Cext : (g_scratch + coff);

    constexpr int BSZ = TRANSB ? 128 * BPT : 16 * BPN;
    __shared__ float As[2][128][AP];
    __shared__ float Bs[2][BSZ];

    const int tid = threadIdx.x;
    const int warp = tid >> 5, lane = tid & 31;
    const int fr = lane >> 2, fc = lane & 3;
    const int wr = warp >> 1;           // 0..3
    const int wc = warp & 1;            // 0..1
    const int mw = wr * 32;
    const int nw = wc * 64;
    const int m0 = blockIdx.y * 128, n0 = blockIdx.x * 128;

    // staging indices
    const int am = tid >> 2;            // 0..63
    const int akq = (tid & 3) * 4;
    // B non-trans: idx = u*256+tid over 512 float4s: row = idx>>5, col4 = (idx&31)*4
    // B trans:     idx = u*256+tid over 512 float4s: n = idx>>2, kq = (idx&3)*4

    float4 pa0, pa1, pb0, pb1;
    {
        pa0 = *(const float4*)(A + (size_t)(m0 + am) * K + akq);
        pa1 = *(const float4*)(A + (size_t)(m0 + am + 64) * K + akq);
        if (TRANSB) {
            int n_0 = tid >> 2, kq = (tid & 3) * 4;
            int n_1 = (256 + tid) >> 2;
            pb0 = *(const float4*)(B + (size_t)(n0 + n_0) * K + kq);
            pb1 = *(const float4*)(B + (size_t)(n0 + n_1) * K + kq);
        } else {
            int r_0 = tid >> 5, c4_0 = (tid & 31) * 4;
            int r_1 = (256 + tid) >> 5, c4_1 = ((256 + tid) & 31) * 4;
            pb0 = *(const float4*)(B + (size_t)r_0 * Nd + n0 + c4_0);
            pb1 = *(const float4*)(B + (size_t)r_1 * Nd + n0 + c4_1);
        }
    }

    float acc[2][8][4];
#pragma unroll
    for (int mf = 0; mf < 2; mf++)
#pragma unroll
        for (int nt = 0; nt < 8; nt++)
#pragma unroll
            for (int j = 0; j < 4; j++) acc[mf][nt][j] = 0.0f;

    const int nk = K >> 4;

    // store tile 0
    {
        As[0][am][akq + 0] = to_tf32(pa0.x);
        As[0][am][akq + 1] = to_tf32(pa0.y);
        As[0][am][akq + 2] = to_tf32(pa0.z);
        As[0][am][akq + 3] = to_tf32(pa0.w);
        As[0][am + 64][akq + 0] = to_tf32(pa1.x);
        As[0][am + 64][akq + 1] = to_tf32(pa1.y);
        As[0][am + 64][akq + 2] = to_tf32(pa1.z);
        As[0][am + 64][akq + 3] = to_tf32(pa1.w);
        if (TRANSB) {
            int n_0 = tid >> 2, kq = (tid & 3) * 4;
            int n_1 = (256 + tid) >> 2;
            float* p0 = &Bs[0][n_0 * BPT + kq];
            float* p1 = &Bs[0][n_1 * BPT + kq];
            p0[0] = to_tf32(pb0.x); p0[1] = to_tf32(pb0.y);
            p0[2] = to_tf32(pb0.z); p0[3] = to_tf32(pb0.w);
            p1[0] = to_tf32(pb1.x); p1[1] = to_tf32(pb1.y);
            p1[2] = to_tf32(pb1.z); p1[3] = to_tf32(pb1.w);
        } else {
            int r_0 = tid >> 5, c4_0 = (tid & 31) * 4;
            int r_1 = (256 + tid) >> 5, c4_1 = ((256 + tid) & 31) * 4;
            float* p0 = &Bs[0][r_0 * BPN + c4_0];
            float* p1 = &Bs[0][r_1 * BPN + c4_1];
            p0[0] = to_tf32(pb0.x); p0[1] = to_tf32(pb0.y);
            p0[2] = to_tf32(pb0.z); p0[3] = to_tf32(pb0.w);
            p1[0] = to_tf32(pb1.x); p1[1] = to_tf32(pb1.y);
            p1[2] = to_tf32(pb1.z); p1[3] = to_tf32(pb1.w);
        }
    }
    __syncthreads();

    for (int k0i = 0; k0i < nk; k0i++) {
        const int cur = k0i & 1, nxt = cur ^ 1;
        const bool more = (k0i + 1) < nk;
        if (more) {
            int k0 = (k0i + 1) << 4;
            pa0 = *(const float4*)(A + (size_t)(m0 + am) * K + k0 + akq);
            pa1 = *(const float4*)(A + (size_t)(m0 + am + 64) * K + k0 + akq);
            if (TRANSB) {
                int n_0 = tid >> 2, kq = (tid & 3) * 4;
                int n_1 = (256 + tid) >> 2;
                pb0 = *(const float4*)(B + (size_t)(n0 + n_0) * K + k0 + kq);
                pb1 = *(const float4*)(B + (size_t)(n0 + n_1) * K + k0 + kq);
            } else {
                int r_0 = tid >> 5, c4_0 = (tid & 31) * 4;
                int r_1 = (256 + tid) >> 5, c4_1 = ((256 + tid) & 31) * 4;
                pb0 = *(const float4*)(B + (size_t)(k0 + r_0) * Nd + n0 + c4_0);
                pb1 = *(const float4*)(B + (size_t)(k0 + r_1) * Nd + n0 + c4_1);
            }
        }

#pragma unroll
        for (int ks = 0; ks < 2; ks++) {
            int kk = ks * 8;
            float a[2][4];
#pragma unroll
            for (int mf = 0; mf < 2; mf++) {
                int row = mw + mf * 16 + fr;
                a[mf][0] = As[cur][row][kk + fc];
                a[mf][1] = As[cur][row + 8][kk + fc];
                a[mf][2] = As[cur][row][kk + fc + 4];
                a[mf][3] = As[cur][row + 8][kk + fc + 4];
            }
#pragma unroll
            for (int nt = 0; nt < 8; nt++) {
                float b0, b1;
                if (TRANSB) {
                    b0 = Bs[cur][(nw + nt * 8 + fr) * BPT + kk + fc];
                    b1 = Bs[cur][(nw + nt * 8 + fr) * BPT + kk + fc + 4];
                } else {
                    b0 = Bs[cur][(kk + fc) * BPN + nw + nt * 8 + fr];
                    b1 = Bs[cur][(kk + fc + 4) * BPN + nw + nt * 8 + fr];
                }
                mma_tf32(acc[0][nt], a[0][0], a[0][1], a[0][2], a[0][3], b0, b1);
                mma_tf32(acc[1][nt], a[1][0], a[1][1], a[1][2], a[1][3], b0, b1);
            }
        }

        if (more) {
            As[nxt][am][akq + 0] = to_tf32(pa0.x);
            As[nxt][am][akq + 1] = to_tf32(pa0.y);
            As[nxt][am][akq + 2] = to_tf32(pa0.z);
            As[nxt][am][akq + 3] = to_tf32(pa0.w);
            As[nxt][am + 64][akq + 0] = to_tf32(pa1.x);
            As[nxt][am + 64][akq + 1] = to_tf32(pa1.y);
            As[nxt][am + 64][akq + 2] = to_tf32(pa1.z);
            As[nxt][am + 64][akq + 3] = to_tf32(pa1.w);
            if (TRANSB) {
                int n_0 = tid >> 2, kq = (tid & 3) * 4;
                int n_1 = (256 + tid) >> 2;
                float* p0 = &Bs[nxt][n_0 * BPT + kq];
                float* p1 = &Bs[nxt][n_1 * BPT + kq];
                p0[0] = to_tf32(pb0.x); p0[1] = to_tf32(pb0.y);
                p0[2] = to_tf32(pb0.z); p0[3] = to_tf32(pb0.w);
                p1[0] = to_tf32(pb1.x); p1[1] = to_tf32(pb1.y);
                p1[2] = to_tf32(pb1.z); p1[3] = to_tf32(pb1.w);
            } else {
                int r_0 = tid >> 5, c4_0 = (tid & 31) * 4;
                int r_1 = (256 + tid) >> 5, c4_1 = ((256 + tid) & 31) * 4;
                float* p0 = &Bs[nxt][r_0 * BPN + c4_0];
                float* p1 = &Bs[nxt][r_1 * BPN + c4_1];
                p0[0] = to_tf32(pb0.x); p0[1] = to_tf32(pb0.y);
                p0[2] = to_tf32(pb0.z); p0[3] = to_tf32(pb0.w);
                p1[0] = to_tf32(pb1.x); p1[1] = to_tf32(pb1.y);
                p1[2] = to_tf32(pb1.z); p1[3] = to_tf32(pb1.w);
            }
            __syncthreads();
        }
    }

    // epilogue
#pragma unroll
    for (int mf = 0; mf < 2; mf++) {
        int r0 = m0 + mw + mf * 16 + fr;
        int r1 = r0 + 8;
#pragma unroll
        for (int nt = 0; nt < 8; nt++) {
            int cc = n0 + nw + nt * 8 + fc * 2;
            float v00 = acc[mf][nt][0], v01 = acc[mf][nt][1];
            float v10 = acc[mf][nt][2], v11 = acc[mf][nt][3];
            if (HASBIAS) {
                float b0 = bias[cc], b1 = bias[cc + 1];
                v00 += b0; v01 += b1; v10 += b0; v11 += b1;
            }
            if (RELU) {
                v00 = fmaxf(v00, 0.0f); v01 = fmaxf(v01, 0.0f);
                v10 = fmaxf(v10, 0.0f); v11 = fmaxf(v11, 0.0f);
            }
            if (OUTBF16) {
                __nv_bfloat162 h0 = __floats2bfloat162_rn(v00, v01);
                __nv_bfloat162 h1 = __floats2bfloat162_rn(v10, v11);
                *(uint32_t*)&g_qkvh[(size_t)r0 * Nd + cc] = *(uint32_t*)&h0;
                *(uint32_t*)&g_qkvh[(size_t)r1 * Nd + cc] = *(uint32_t*)&h1;
            } else {
                *(float2*)&C[(size_t)r0 * Nd + cc] = make_float2(v00, v01);
                *(float2*)&C[(size_t)r1 * Nd + cc] = make_float2(v10, v11);
            }
        }
    }
}

// ---------------- bf16 tensor-core flash attention (split-K) ----------------
__device__ __forceinline__ void mma_bf16(float c[4], uint32_t a0, uint32_t a1,
                                         uint32_t a2, uint32_t a3,
                                         uint32_t b0, uint32_t b1) {
    asm volatile(
        "mma.sync.aligned.m16n8k16.row.col.f32.bf16.bf16.f32 "
        "{%0,%1,%2,%3},{%4,%5,%6,%7},{%8,%9},{%0,%1,%2,%3};\n"
        : "+f"(c[0]), "+f"(c[1]), "+f"(c[2]), "+f"(c[3])
        : "r"(a0), "r"(a1), "r"(a2), "r"(a3), "r"(b0), "r"(b1));
}

#define FA_PITCH 72
#define KB_PER_SPLIT (NN / 64 / SPLITS)  // 16

__global__ __launch_bounds__(128) void flash_attn_split_kernel() {
    const __nv_bfloat16* __restrict__ qkvh = g_qkvh;
    const int head = blockIdx.y;
    const int split = blockIdx.z;
    const int q0 = blockIdx.x * 64;
    const int tid = threadIdx.x;
    const int warp = tid >> 5;
    const int lane = tid & 31;
    const int quad = lane >> 2;
    const int qd = lane & 3;

    __shared__ __align__(16) __nv_bfloat16 Qs[64][FA_PITCH];
    __shared__ __align__(16) __nv_bfloat16 Ks[64][FA_PITCH];
    __shared__ __align__(16) __nv_bfloat16 Vt[64][FA_PITCH];
    __shared__ __align__(16) __nv_bfloat16 Ps[64][FA_PITCH];

#pragma unroll
    for (int ch = 0; ch < 4; ch++) {
        int idx = ch * 128 + tid;
        int r = idx >> 3;
        int c = (idx & 7) * 8;
        *(uint4*)&Qs[r][c] =
            *(const uint4*)&qkvh[(size_t)(q0 + r) * 768 + head * 64 + c];
    }

    float m0r = -1e30f, m1r = -1e30f;
    float l0r = 0.0f, l1r = 0.0f;
    float o[8][4];
#pragma unroll
    for (int nt = 0; nt < 8; nt++)
#pragma unroll
        for (int j = 0; j < 4; j++) o[nt][j] = 0.0f;

    const int qrowA = warp * 16 + quad;
    const int qrowB = qrowA + 8;

    const int kb_beg = split * KB_PER_SPLIT;
    for (int kb = kb_beg; kb < kb_beg + KB_PER_SPLIT; kb++) {
        int kbase = kb * 64;
        __syncthreads();
#pragma unroll
        for (int ch = 0; ch < 4; ch++) {
            int idx = ch * 128 + tid;
            int r = idx >> 3;
            int c = (idx & 7) * 8;
            *(uint4*)&Ks[r][c] =
                *(const uint4*)&qkvh[(size_t)(kbase + r) * 768 + 256 + head * 64 + c];
        }
        {
            int r = tid & 63;
            int d0 = (tid >> 6) * 32;
#pragma unroll
            for (int u = 0; u < 4; u++) {
                uint4 vv = *(const uint4*)&qkvh[(size_t)(kbase + r) * 768 + 512 +
                                                head * 64 + d0 + u * 8];
                __nv_bfloat16 tmp[8];
                *(uint4*)tmp = vv;
#pragma unroll
                for (int j = 0; j < 8; j++) Vt[d0 + u * 8 + j][r] = tmp[j];
            }
        }
        __syncthreads();

        float sc[8][4];
#pragma unroll
        for (int nt = 0; nt < 8; nt++)
#pragma unroll
            for (int j = 0; j < 4; j++) sc[nt][j] = 0.0f;

#pragma unroll
        for (int ks = 0; ks < 4; ks++) {
            int k0 = ks * 16;
            uint32_t a0 = *(const uint32_t*)&Qs[qrowA][k0 + qd * 2];
            uint32_t a1 = *(const uint32_t*)&Qs[qrowB][k0 + qd * 2];
            uint32_t a2 = *(const uint32_t*)&Qs[qrowA][k0 + qd * 2 + 8];
            uint32_t a3 = *(const uint32_t*)&Qs[qrowB][k0 + qd * 2 + 8];
#pragma unroll
            for (int nt = 0; nt < 8; nt++) {
                uint32_t b0 = *(const uint32_t*)&Ks[nt * 8 + quad][k0 + qd * 2];
                uint32_t b1 = *(const uint32_t*)&Ks[nt * 8 + quad][k0 + qd * 2 + 8];
                mma_bf16(sc[nt], a0, a1, a2, a3, b0, b1);
            }
        }

        float mA = -1e30f, mB = -1e30f;
#pragma unroll
        for (int nt = 0; nt < 8; nt++) {
            sc[nt][0] *= 0.125f; sc[nt][1] *= 0.125f;
            sc[nt][2] *= 0.125f; sc[nt][3] *= 0.125f;
            mA = fmaxf(mA, fmaxf(sc[nt][0], sc[nt][1]));
            mB = fmaxf(mB, fmaxf(sc[nt][2], sc[nt][3]));
        }
        mA = fmaxf(mA, __shfl_xor_sync(0xffffffffu, mA, 1));
        mA = fmaxf(mA, __shfl_xor_sync(0xffffffffu, mA, 2));
        mB = fmaxf(mB, __shfl_xor_sync(0xffffffffu, mB, 1));
        mB = fmaxf(mB, __shfl_xor_sync(0xffffffffu, mB, 2));
        float mnA = fmaxf(m0r, mA);
        float mnB = fmaxf(m1r, mB);
        float alA = __expf(m0r - mnA);
        float alB = __expf(m1r - mnB);
        float sumA = 0.0f, sumB = 0.0f;
#pragma unroll
        for (int nt = 0; nt < 8; nt++) {
            float p0 = __expf(sc[nt][0] - mnA);
            float p1 = __expf(sc[nt][1] - mnA);
            float p2 = __expf(sc[nt][2] - mnB);
            float p3 = __expf(sc[nt][3] - mnB);
            sumA += p0 + p1;
            sumB += p2 + p3;
            __nv_bfloat162 hA = __floats2bfloat162_rn(p0, p1);
            __nv_bfloat162 hB = __floats2bfloat162_rn(p2, p3);
            *(uint32_t*)&Ps[qrowA][nt * 8 + qd * 2] = *(uint32_t*)&hA;
            *(uint32_t*)&Ps[qrowB][nt * 8 + qd * 2] = *(uint32_t*)&hB;
        }
        sumA += __shfl_xor_sync(0xffffffffu, sumA, 1);
        sumA += __shfl_xor_sync(0xffffffffu, sumA, 2);
        sumB += __shfl_xor_sync(0xffffffffu, sumB, 1);
        sumB += __shfl_xor_sync(0xffffffffu, sumB, 2);
        l0r = l0r * alA + sumA;
        l1r = l1r * alB + sumB;
        m0r = mnA;
        m1r = mnB;
#pragma unroll
        for (int nt = 0; nt < 8; nt++) {
            o[nt][0] *= alA; o[nt][1] *= alA;
            o[nt][2] *= alB; o[nt][3] *= alB;
        }
        __syncwarp();

#pragma unroll
        for (int ks = 0; ks < 4; ks++) {
            int k0 = ks * 16;
            uint32_t a0 = *(const uint32_t*)&Ps[qrowA][k0 + qd * 2];
            uint32_t a1 = *(const uint32_t*)&Ps[qrowB][k0 + qd * 2];
            uint32_t a2 = *(const uint32_t*)&Ps[qrowA][k0 + qd * 2 + 8];
            uint32_t a3 = *(const uint32_t*)&Ps[qrowB][k0 + qd * 2 + 8];
#pragma unroll
            for (int nt = 0; nt < 8; nt++) {
                uint32_t b0 = *(const uint32_t*)&Vt[nt * 8 + quad][k0 + qd * 2];
                uint32_t b1 = *(const uint32_t*)&Vt[nt * 8 + quad][k0 + qd * 2 + 8];
                mma_bf16(o[nt], a0, a1, a2, a3, b0, b1);
            }
        }
    }

    float* __restrict__ po = g_scratch + OFF_PARTO + (long)split * NN * IN_DIM;
    int gA = q0 + qrowA;
    int gB = q0 + qrowB;
#pragma unroll
    for (int nt = 0; nt < 8; nt++) {
        *(float2*)&po[(size_t)gA * IN_DIM + head * 64 + nt * 8 + qd * 2] =
            make_float2(o[nt][0], o[nt][1]);
        *(float2*)&po[(size_t)gB * IN_DIM + head * 64 + nt * 8 + qd * 2] =
            make_float2(o[nt][2], o[nt][3]);
    }
    if (qd == 0) {
        long mlbase = OFF_PARTML + ((long)split * HEADS + head) * NN;
        long lbase = mlbase + (long)SPLITS * HEADS * NN;
        g_scratch[mlbase + gA] = m0r;
        g_scratch[mlbase + gB] = m1r;
        g_scratch[lbase + gA] = l0r;
        g_scratch[lbase + gB] = l1r;
    }
}

__global__ __launch_bounds__(256) void attn_combine_kernel() {
    int idx = blockIdx.x * 256 + threadIdx.x;
    int dq = idx & 15;
    int h = (idx >> 4) & (HEADS - 1);
    int row = idx >> 6;

    float m[SPLITS], l[SPLITS];
    float M = -1e30f;
#pragma unroll
    for (int s = 0; s < SPLITS; s++) {
        long mlbase = OFF_PARTML + ((long)s * HEADS + h) * NN;
        m[s] = g_scratch[mlbase + row];
        l[s] = g_scratch[mlbase + (long)SPLITS * HEADS * NN + row];
        M = fmaxf(M, m[s]);
    }
    float L = 0.0f;
    float4 acc = make_float4(0.0f, 0.0f, 0.0f, 0.0f);
#pragma unroll
    for (int s = 0; s < SPLITS; s++) {
        float w = __expf(m[s] - M);
        L += l[s] * w;
        const float* po = g_scratch + OFF_PARTO + (long)s * NN * IN_DIM;
        float4 v = *(const float4*)&po[(size_t)row * IN_DIM + h * 64 + dq * 4];
        acc.x += v.x * w; acc.y += v.y * w;
        acc.z += v.z * w; acc.w += v.w * w;
    }
    float inv = 1.0f / L;
    acc.x *= inv; acc.y *= inv; acc.z *= inv; acc.w *= inv;
    *(float4*)&g_scratch[OFF_COMBO + (size_t)row * 768 + 512 + h * 64 + dq * 4] = acc;
}

// ---------------- launch (single stream, sequential) ----------------
extern "C" void kernel_launch(void* const* d_in, const int* in_sizes, int n_in,
                              void* d_out, int out_size) {
    const float* x          = (const float*)d_in[0];
    const int*   ei         = (const int*)d_in[1];
    const float* gcn1_w     = (const float*)d_in[2];
    const float* gcn1_b     = (const float*)d_in[3];
    const float* gcn2_w     = (const float*)d_in[4];
    const float* gcn2_b     = (const float*)d_in[5];
    const float* lin_w      = (const float*)d_in[6];
    const float* lin_b      = (const float*)d_in[7];
    const float* in_proj_w  = (const float*)d_in[8];
    const float* in_proj_b  = (const float*)d_in[9];
    const float* out_proj_w = (const float*)d_in[10];
    const float* out_proj_b = (const float*)d_in[11];
    const float* proj_w     = (const float*)d_in[12];
    const float* proj_b     = (const float*)d_in[13];
    float* out = (float*)d_out;

    // CSR build + dinv (g_cnt starts 0; fill consumes it back to 0)
    hist_kernel<<<EE / 256, 256>>>(ei);
    scan_kernel<<<1, 1024>>>();
    fill_kernel<<<EE / 256, 256>>>(ei);

    // weight folding
    copy_linw_kernel<<<(HIDDEN * CLASSES / 4) / 256, 256>>>(lin_w);
    wprime_kernel<<<256, 256>>>(out_proj_w, proj_w);
    btot_kernel<<<1, 256>>>(lin_b, out_proj_b, proj_w, proj_b);

    // transformer: qkv (bf16 out) -> split-K flash attention -> combine
    gemm_tc<true, false, true, true><<<dim3((3 * IN_DIM) / 128, NN / 128), 256>>>(
        x, 0L, in_proj_w, 0L, in_proj_b, 0L, nullptr, 0L, NN, IN_DIM, 3 * IN_DIM);
    flash_attn_split_kernel<<<dim3(NN / 64, HEADS, SPLITS), 128>>>();
    attn_combine_kernel<<<(NN * HEADS * 16) / 256, 256>>>();

    // GNN: aggregate-first conv1
    gather_kernel<false><<<dim3(NN / 8, IN_DIM / 128), 256>>>(
        x, 0L, nullptr, OFF_AGGX, IN_DIM, IN_DIM, 0);
    gemm_tc<false, true, true, false><<<dim3(HIDDEN / 128, NN / 128), 256>>>(
        nullptr, OFF_AGGX, gcn1_w, 0L, gcn1_b, 0L, nullptr, OFF_AGG1, NN, IN_DIM, HIDDEN);

    gemm_tc<false, false, false, false><<<dim3(HIDDEN / 128, NN / 128), 256>>>(
        nullptr, OFF_AGG1, gcn2_w, 0L, nullptr, 0L, nullptr, OFF_H2, NN, HIDDEN, HIDDEN);
    gather_kernel<true><<<dim3(NN / 8, HIDDEN / 128), 256>>>(
        nullptr, OFF_H2, gcn2_b, OFF_COMBO, HIDDEN, 768, 0);

    // out = relu([agg2 | attn] @ comboW + b_tot)
    gemm_tc<false, true, true, false><<<dim3(CLASSES / 128, NN / 128), 256>>>(
        nullptr, OFF_COMBO, nullptr, OFF_COMBOW, nullptr, OFF_BTOT, out, 0L, NN, 768, CLASSES);
}

// round 16
// speedup vs baseline: 1.3603x; 1.1149x over previous
#include <cuda_runtime.h>
#include <cuda_bf16.h>
#include <math.h>
#include <stdint.h>

#define NN 4096
#define IN_DIM 256
#define HIDDEN 512
#define CLASSES 256
#define HEADS 4
#define HD 64
#define EE 131072
#define SPLITS 4

// ---------------- scratch ----------------
#define OFF_DINV   0L
#define OFF_AGGX   (OFF_DINV + NN)
#define OFF_AGG1   (OFF_AGGX + (long)NN * IN_DIM)
#define OFF_H2     (OFF_AGG1 + (long)NN * HIDDEN)
#define OFF_COMBO  (OFF_H2   + (long)NN * HIDDEN)
#define OFF_COMBOW (OFF_COMBO + (long)NN * 768)
#define OFF_BTOT   (OFF_COMBOW + 768L * 256)
#define OFF_PARTO  (OFF_BTOT + 256)
#define OFF_PARTML (OFF_PARTO + (long)SPLITS * NN * IN_DIM)
#define SCRATCH_TOTAL (OFF_PARTML + 2L * SPLITS * HEADS * NN)

__device__ __align__(16) float g_scratch[SCRATCH_TOTAL];
__device__ __align__(16) __nv_bfloat16 g_qkvh[(long)NN * 3 * IN_DIM];
__device__ int g_cnt[NN];         // zero-init; returns to 0 after each full pass
__device__ int g_rowptr[NN + 1];
__device__ int g_srcidx[EE];

// ---------------- CSR build ----------------
__global__ void hist_kernel(const int* __restrict__ ei) {
    int i = blockIdx.x * blockDim.x + threadIdx.x;
    if (i < EE) atomicAdd(&g_cnt[ei[EE + i]], 1);
}
__global__ __launch_bounds__(1024) void scan_kernel() {
    __shared__ int sh[1024];
    int t = threadIdx.x;
    int base = t * 4;
    int c0 = g_cnt[base + 0], c1 = g_cnt[base + 1];
    int c2 = g_cnt[base + 2], c3 = g_cnt[base + 3];
    int s = c0 + c1 + c2 + c3;
    sh[t] = s;
    __syncthreads();
    for (int off = 1; off < 1024; off <<= 1) {
        int v = (t >= off) ? sh[t - off] : 0;
        __syncthreads();
        sh[t] += v;
        __syncthreads();
    }
    int run = sh[t] - s;
    g_rowptr[base + 0] = run;            run += c0;
    g_rowptr[base + 1] = run;            run += c1;
    g_rowptr[base + 2] = run;            run += c2;
    g_rowptr[base + 3] = run;            run += c3;
    if (t == 1023) g_rowptr[NN] = run;
    g_scratch[OFF_DINV + base + 0] = rsqrtf((float)c0 + 1.0f);
    g_scratch[OFF_DINV + base + 1] = rsqrtf((float)c1 + 1.0f);
    g_scratch[OFF_DINV + base + 2] = rsqrtf((float)c2 + 1.0f);
    g_scratch[OFF_DINV + base + 3] = rsqrtf((float)c3 + 1.0f);
}
__global__ void fill_kernel(const int* __restrict__ ei) {
    int e = blockIdx.x * blockDim.x + threadIdx.x;
    if (e >= EE) return;
    int dst = ei[EE + e];
    int pos = g_rowptr[dst] + atomicSub(&g_cnt[dst], 1) - 1;
    g_srcidx[pos] = ei[e];
}

// ---------------- fused GCN aggregation (gather) ----------------
template <bool BIASRELU>
__global__ __launch_bounds__(256) void gather_kernel(const float* __restrict__ hext, long hoff,
                                                     const float* __restrict__ bias,
                                                     long aggoff, int F, int ostride, int coloff) {
    const float* __restrict__ h = hext ? hext : (const float*)(g_scratch + hoff);
    float* __restrict__ agg = g_scratch + aggoff;
    const float* __restrict__ dinv = g_scratch + OFF_DINV;
    const int warp = threadIdx.x >> 5;
    const int lane = threadIdx.x & 31;
    const int node = blockIdx.x * 8 + warp;
    const int c = blockIdx.y * 128 + lane * 4;

    float dd = dinv[node];
    float4 hv = *(const float4*)&h[(size_t)node * F + c];
    float sw = dd * dd;
    float4 acc = make_float4(hv.x * sw, hv.y * sw, hv.z * sw, hv.w * sw);
    if (BIASRELU) {
        float4 b4 = *(const float4*)&bias[c];
        acc.x += b4.x; acc.y += b4.y; acc.z += b4.z; acc.w += b4.w;
    }

    int beg = g_rowptr[node];
    int end = g_rowptr[node + 1];
    int j = beg;
    for (; j + 4 <= end; j += 4) {
        int s0 = g_srcidx[j], s1 = g_srcidx[j + 1];
        int s2 = g_srcidx[j + 2], s3 = g_srcidx[j + 3];
        float w0 = dinv[s0] * dd, w1 = dinv[s1] * dd;
        float w2 = dinv[s2] * dd, w3 = dinv[s3] * dd;
        float4 v0 = *(const float4*)&h[(size_t)s0 * F + c];
        float4 v1 = *(const float4*)&h[(size_t)s1 * F + c];
        float4 v2 = *(const float4*)&h[(size_t)s2 * F + c];
        float4 v3 = *(const float4*)&h[(size_t)s3 * F + c];
        acc.x += v0.x * w0 + v1.x * w1 + v2.x * w2 + v3.x * w3;
        acc.y += v0.y * w0 + v1.y * w1 + v2.y * w2 + v3.y * w3;
        acc.z += v0.z * w0 + v1.z * w1 + v2.z * w2 + v3.z * w3;
        acc.w += v0.w * w0 + v1.w * w1 + v2.w * w2 + v3.w * w3;
    }
    for (; j < end; j++) {
        int s0 = g_srcidx[j];
        float w0 = dinv[s0] * dd;
        float4 v0 = *(const float4*)&h[(size_t)s0 * F + c];
        acc.x += v0.x * w0; acc.y += v0.y * w0;
        acc.z += v0.z * w0; acc.w += v0.w * w0;
    }
    if (BIASRELU) {
        acc.x = fmaxf(acc.x, 0.0f); acc.y = fmaxf(acc.y, 0.0f);
        acc.z = fmaxf(acc.z, 0.0f); acc.w = fmaxf(acc.w, 0.0f);
    }
    *(float4*)&agg[(size_t)node * ostride + coloff + c] = acc;
}

// ---------------- fused weight-fold kernel ----------------
// blocks 0..127: copy lin_w chunk; 128..383: wprime row; 384: btot
__global__ __launch_bounds__(256) void fold_kernel(const float* __restrict__ lin_w,
                                                   const float* __restrict__ out_w,
                                                   const float* __restrict__ proj_w,
                                                   const float* __restrict__ lin_b,
                                                   const float* __restrict__ out_b,
                                                   const float* __restrict__ proj_b) {
    int bid = blockIdx.x;
    int t = threadIdx.x;
    if (bid < 128) {
        int i = bid * 256 + t;  // over 512*256/4 = 32768 float4s
        float4 v = *(const float4*)&lin_w[4L * i];
        *(float4*)&g_scratch[OFF_COMBOW + 4L * i] = v;
    } else if (bid < 384) {
        int i = bid - 128;
        float acc = 0.0f;
#pragma unroll 4
        for (int k = 0; k < 256; k++)
            acc += __ldg(&out_w[k * 256 + i]) * proj_w[k * 256 + t];
        g_scratch[OFF_COMBOW + (512L + i) * 256 + t] = acc;
    } else {
        float acc = lin_b[t] + proj_b[t];
#pragma unroll 4
        for (int k = 0; k < 256; k++)
            acc += __ldg(&out_b[k]) * proj_w[k * 256 + t];
        g_scratch[OFF_BTOT + t] = acc;
    }
}

// ---------------- tf32 helpers ----------------
__device__ __forceinline__ float to_tf32(float x) {
    float r;
    asm("cvt.rna.tf32.f32 %0, %1;" : "=f"(r) : "f"(x));
    return r;
}
__device__ __forceinline__ void mma_tf32(float c[4], float a0, float a1, float a2,
                                         float a3, float b0, float b1) {
    uint32_t ua0 = __float_as_uint(a0), ua1 = __float_as_uint(a1);
    uint32_t ua2 = __float_as_uint(a2), ua3 = __float_as_uint(a3);
    uint32_t ub0 = __float_as_uint(b0), ub1 = __float_as_uint(b1);
    asm volatile(
        "mma.sync.aligned.m16n8k8.row.col.f32.tf32.tf32.f32 "
        "{%0,%1,%2,%3},{%4,%5,%6,%7},{%8,%9},{%0,%1,%2,%3};\n"
        : "+f"(c[0]), "+f"(c[1]), "+f"(c[2]), "+f"(c[3])
        : "r"(ua0), "r"(ua1), "r"(ua2), "r"(ua3), "r"(ub0), "r"(ub1));
}

// ---------------- tf32 GEMM: BM=64 BN=128 BK=16, 8 warps (2x4) ----------------
#define AP 20
#define BPN 132
#define BPT 20
template <bool TRANSB, bool RELU, bool HASBIAS, bool OUTBF16>
__global__ __launch_bounds__(256) void gemm_tc(const float* __restrict__ Aext, long aoff,
                                               const float* __restrict__ Bext, long boff,
                                               const float* __restrict__ biasext, long biasoff,
                                               float* __restrict__ Cext, long coff,
                                               int M, int K, int Nd) {
    const float* __restrict__ A = Aext ? Aext : (const float*)(g_scratch + aoff);
    const float* __restrict__ B = Bext ? Bext : (const float*)(g_scratch + boff);
    const float* __restrict__ bias = HASBIAS ? (biasext ? biasext : (const float*)(g_scratch + biasoff)) : nullptr;
    float* __restrict__ C = Cext ? Cext : (g_scratch + coff);

    constexpr int BSZ = TRANSB ? 128 * BPT : 16 * BPN;
    __shared__ float As[2][64][AP];
    __shared__ float Bs[2][BSZ];

    const int tid = threadIdx.x;
    const int warp = tid >> 5, lane = tid & 31;
    const int fr = lane >> 2, fc = lane & 3;
    const int wr = warp >> 2;           // 0..1
    const int wc = warp & 3;            // 0..3
    const int mw = wr * 32;
    const int nw = wc * 32;
    const int m0 = blockIdx.y * 64, n0 = blockIdx.x * 128;

    const int am = tid >> 2;            // 0..63
    const int akq = (tid & 3) * 4;

    float4 pa0, pb0, pb1;
    {
        pa0 = *(const float4*)(A + (size_t)(m0 + am) * K + akq);
        if (TRANSB) {
            int n_0 = tid >> 2, kq = (tid & 3) * 4;
            int n_1 = (256 + tid) >> 2;
            pb0 = *(const float4*)(B + (size_t)(n0 + n_0) * K + kq);
            pb1 = *(const float4*)(B + (size_t)(n0 + n_1) * K + kq);
        } else {
            int r_0 = tid >> 5, c4_0 = (tid & 31) * 4;
            int r_1 = (256 + tid) >> 5, c4_1 = ((256 + tid) & 31) * 4;
            pb0 = *(const float4*)(B + (size_t)r_0 * Nd + n0 + c4_0);
            pb1 = *(const float4*)(B + (size_t)r_1 * Nd + n0 + c4_1);
        }
    }

    float acc[2][4][4];
#pragma unroll
    for (int mf = 0; mf < 2; mf++)
#pragma unroll
        for (int nt = 0; nt < 4; nt++)
#pragma unroll
            for (int j = 0; j < 4; j++) acc[mf][nt][j] = 0.0f;

    const int nk = K >> 4;

    {
        As[0][am][akq + 0] = to_tf32(pa0.x);
        As[0][am][akq + 1] = to_tf32(pa0.y);
        As[0][am][akq + 2] = to_tf32(pa0.z);
        As[0][am][akq + 3] = to_tf32(pa0.w);
        if (TRANSB) {
            int n_0 = tid >> 2, kq = (tid & 3) * 4;
            int n_1 = (256 + tid) >> 2;
            float* p0 = &Bs[0][n_0 * BPT + kq];
            float* p1 = &Bs[0][n_1 * BPT + kq];
            p0[0] = to_tf32(pb0.x); p0[1] = to_tf32(pb0.y);
            p0[2] = to_tf32(pb0.z); p0[3] = to_tf32(pb0.w);
            p1[0] = to_tf32(pb1.x); p1[1] = to_tf32(pb1.y);
            p1[2] = to_tf32(pb1.z); p1[3] = to_tf32(pb1.w);
        } else {
            int r_0 = tid >> 5, c4_0 = (tid & 31) * 4;
            int r_1 = (256 + tid) >> 5, c4_1 = ((256 + tid) & 31) * 4;
            float* p0 = &Bs[0][r_0 * BPN + c4_0];
            float* p1 = &Bs[0][r_1 * BPN + c4_1];
            p0[0] = to_tf32(pb0.x); p0[1] = to_tf32(pb0.y);
            p0[2] = to_tf32(pb0.z); p0[3] = to_tf32(pb0.w);
            p1[0] = to_tf32(pb1.x); p1[1] = to_tf32(pb1.y);
            p1[2] = to_tf32(pb1.z); p1[3] = to_tf32(pb1.w);
        }
    }
    __syncthreads();

    for (int k0i = 0; k0i < nk; k0i++) {
        const int cur = k0i & 1, nxt = cur ^ 1;
        const bool more = (k0i + 1) < nk;
        if (more) {
            int k0 = (k0i + 1) << 4;
            pa0 = *(const float4*)(A + (size_t)(m0 + am) * K + k0 + akq);
            if (TRANSB) {
                int n_0 = tid >> 2, kq = (tid & 3) * 4;
                int n_1 = (256 + tid) >> 2;
                pb0 = *(const float4*)(B + (size_t)(n0 + n_0) * K + k0 + kq);
                pb1 = *(const float4*)(B + (size_t)(n0 + n_1) * K + k0 + kq);
            } else {
                int r_0 = tid >> 5, c4_0 = (tid & 31) * 4;
                int r_1 = (256 + tid) >> 5, c4_1 = ((256 + tid) & 31) * 4;
                pb0 = *(const float4*)(B + (size_t)(k0 + r_0) * Nd + n0 + c4_0);
                pb1 = *(const float4*)(B + (size_t)(k0 + r_1) * Nd + n0 + c4_1);
            }
        }

#pragma unroll
        for (int ks = 0; ks < 2; ks++) {
            int kk = ks * 8;
            float a[2][4];
#pragma unroll
            for (int mf = 0; mf < 2; mf++) {
                int row = mw + mf * 16 + fr;
                a[mf][0] = As[cur][row][kk + fc];
                a[mf][1] = As[cur][row + 8][kk + fc];
                a[mf][2] = As[cur][row][kk + fc + 4];
                a[mf][3] = As[cur][row + 8][kk + fc + 4];
            }
#pragma unroll
            for (int nt = 0; nt < 4; nt++) {
                float b0, b1;
                if (TRANSB) {
                    b0 = Bs[cur][(nw + nt * 8 + fr) * BPT + kk + fc];
                    b1 = Bs[cur][(nw + nt * 8 + fr) * BPT + kk + fc + 4];
                } else {
                    b0 = Bs[cur][(kk + fc) * BPN + nw + nt * 8 + fr];
                    b1 = Bs[cur][(kk + fc + 4) * BPN + nw + nt * 8 + fr];
                }
                mma_tf32(acc[0][nt], a[0][0], a[0][1], a[0][2], a[0][3], b0, b1);
                mma_tf32(acc[1][nt], a[1][0], a[1][1], a[1][2], a[1][3], b0, b1);
            }
        }

        if (more) {
            As[nxt][am][akq + 0] = to_tf32(pa0.x);
            As[nxt][am][akq + 1] = to_tf32(pa0.y);
            As[nxt][am][akq + 2] = to_tf32(pa0.z);
            As[nxt][am][akq + 3] = to_tf32(pa0.w);
            if (TRANSB) {
                int n_0 = tid >> 2, kq = (tid & 3) * 4;
                int n_1 = (256 + tid) >> 2;
                float* p0 = &Bs[nxt][n_0 * BPT + kq];
                float* p1 = &Bs[nxt][n_1 * BPT + kq];
                p0[0] = to_tf32(pb0.x); p0[1] = to_tf32(pb0.y);
                p0[2] = to_tf32(pb0.z); p0[3] = to_tf32(pb0.w);
                p1[0] = to_tf32(pb1.x); p1[1] = to_tf32(pb1.y);
                p1[2] = to_tf32(pb1.z); p1[3] = to_tf32(pb1.w);
            } else {
                int r_0 = tid >> 5, c4_0 = (tid & 31) * 4;
                int r_1 = (256 + tid) >> 5, c4_1 = ((256 + tid) & 31) * 4;
                float* p0 = &Bs[nxt][r_0 * BPN + c4_0];
                float* p1 = &Bs[nxt][r_1 * BPN + c4_1];
                p0[0] = to_tf32(pb0.x); p0[1] = to_tf32(pb0.y);
                p0[2] = to_tf32(pb0.z); p0[3] = to_tf32(pb0.w);
                p1[0] = to_tf32(pb1.x); p1[1] = to_tf32(pb1.y);
                p1[2] = to_tf32(pb1.z); p1[3] = to_tf32(pb1.w);
            }
            __syncthreads();
        }
    }

    // epilogue
#pragma unroll
    for (int mf = 0; mf < 2; mf++) {
        int r0 = m0 + mw + mf * 16 + fr;
        int r1 = r0 + 8;
#pragma unroll
        for (int nt = 0; nt < 4; nt++) {
            int cc = n0 + nw + nt * 8 + fc * 2;
            float v00 = acc[mf][nt][0], v01 = acc[mf][nt][1];
            float v10 = acc[mf][nt][2], v11 = acc[mf][nt][3];
            if (HASBIAS) {
                float b0 = bias[cc], b1 = bias[cc + 1];
                v00 += b0; v01 += b1; v10 += b0; v11 += b1;
            }
            if (RELU) {
                v00 = fmaxf(v00, 0.0f); v01 = fmaxf(v01, 0.0f);
                v10 = fmaxf(v10, 0.0f); v11 = fmaxf(v11, 0.0f);
            }
            if (OUTBF16) {
                __nv_bfloat162 h0 = __floats2bfloat162_rn(v00, v01);
                __nv_bfloat162 h1 = __floats2bfloat162_rn(v10, v11);
                *(uint32_t*)&g_qkvh[(size_t)r0 * Nd + cc] = *(uint32_t*)&h0;
                *(uint32_t*)&g_qkvh[(size_t)r1 * Nd + cc] = *(uint32_t*)&h1;
            } else {
                *(float2*)&C[(size_t)r0 * Nd + cc] = make_float2(v00, v01);
                *(float2*)&C[(size_t)r1 * Nd + cc] = make_float2(v10, v11);
            }
        }
    }
}

// ---------------- bf16 tensor-core flash attention (split-K) ----------------
__device__ __forceinline__ void mma_bf16(float c[4], uint32_t a0, uint32_t a1,
                                         uint32_t a2, uint32_t a3,
                                         uint32_t b0, uint32_t b1) {
    asm volatile(
        "mma.sync.aligned.m16n8k16.row.col.f32.bf16.bf16.f32 "
        "{%0,%1,%2,%3},{%4,%5,%6,%7},{%8,%9},{%0,%1,%2,%3};\n"
        : "+f"(c[0]), "+f"(c[1]), "+f"(c[2]), "+f"(c[3])
        : "r"(a0), "r"(a1), "r"(a2), "r"(a3), "r"(b0), "r"(b1));
}

#define FA_PITCH 72
#define KB_PER_SPLIT (NN / 64 / SPLITS)  // 16

__global__ __launch_bounds__(128) void flash_attn_split_kernel() {
    const __nv_bfloat16* __restrict__ qkvh = g_qkvh;
    const int head = blockIdx.y;
    const int split = blockIdx.z;
    const int q0 = blockIdx.x * 64;
    const int tid = threadIdx.x;
    const int warp = tid >> 5;
    const int lane = tid & 31;
    const int quad = lane >> 2;
    const int qd = lane & 3;

    __shared__ __align__(16) __nv_bfloat16 Qs[64][FA_PITCH];
    __shared__ __align__(16) __nv_bfloat16 Ks[64][FA_PITCH];
    __shared__ __align__(16) __nv_bfloat16 Vt[64][FA_PITCH];
    __shared__ __align__(16) __nv_bfloat16 Ps[64][FA_PITCH];

#pragma unroll
    for (int ch = 0; ch < 4; ch++) {
        int idx = ch * 128 + tid;
        int r = idx >> 3;
        int c = (idx & 7) * 8;
        *(uint4*)&Qs[r][c] =
            *(const uint4*)&qkvh[(size_t)(q0 + r) * 768 + head * 64 + c];
    }

    float m0r = -1e30f, m1r = -1e30f;
    float l0r = 0.0f, l1r = 0.0f;
    float o[8][4];
#pragma unroll
    for (int nt = 0; nt < 8; nt++)
#pragma unroll
        for (int j = 0; j < 4; j++) o[nt][j] = 0.0f;

    const int qrowA = warp * 16 + quad;
    const int qrowB = qrowA + 8;

    const int kb_beg = split * KB_PER_SPLIT;
    for (int kb = kb_beg; kb < kb_beg + KB_PER_SPLIT; kb++) {
        int kbase = kb * 64;
        __syncthreads();
#pragma unroll
        for (int ch = 0; ch < 4; ch++) {
            int idx = ch * 128 + tid;
            int r = idx >> 3;
            int c = (idx & 7) * 8;
            *(uint4*)&Ks[r][c] =
                *(const uint4*)&qkvh[(size_t)(kbase + r) * 768 + 256 + head * 64 + c];
        }
        {
            int r = tid & 63;
            int d0 = (tid >> 6) * 32;
#pragma unroll
            for (int u = 0; u < 4; u++) {
                uint4 vv = *(const uint4*)&qkvh[(size_t)(kbase + r) * 768 + 512 +
                                                head * 64 + d0 + u * 8];
                __nv_bfloat16 tmp[8];
                *(uint4*)tmp = vv;
#pragma unroll
                for (int j = 0; j < 8; j++) Vt[d0 + u * 8 + j][r] = tmp[j];
            }
        }
        __syncthreads();

        float sc[8][4];
#pragma unroll
        for (int nt = 0; nt < 8; nt++)
#pragma unroll
            for (int j = 0; j < 4; j++) sc[nt][j] = 0.0f;

#pragma unroll
        for (int ks = 0; ks < 4; ks++) {
            int k0 = ks * 16;
            uint32_t a0 = *(const uint32_t*)&Qs[qrowA][k0 + qd * 2];
            uint32_t a1 = *(const uint32_t*)&Qs[qrowB][k0 + qd * 2];
            uint32_t a2 = *(const uint32_t*)&Qs[qrowA][k0 + qd * 2 + 8];
            uint32_t a3 = *(const uint32_t*)&Qs[qrowB][k0 + qd * 2 + 8];
#pragma unroll
            for (int nt = 0; nt < 8; nt++) {
                uint32_t b0 = *(const uint32_t*)&Ks[nt * 8 + quad][k0 + qd * 2];
                uint32_t b1 = *(const uint32_t*)&Ks[nt * 8 + quad][k0 + qd * 2 + 8];
                mma_bf16(sc[nt], a0, a1, a2, a3, b0, b1);
            }
        }

        float mA = -1e30f, mB = -1e30f;
#pragma unroll
        for (int nt = 0; nt < 8; nt++) {
            sc[nt][0] *= 0.125f; sc[nt][1] *= 0.125f;
            sc[nt][2] *= 0.125f; sc[nt][3] *= 0.125f;
            mA = fmaxf(mA, fmaxf(sc[nt][0], sc[nt][1]));
            mB = fmaxf(mB, fmaxf(sc[nt][2], sc[nt][3]));
        }
        mA = fmaxf(mA, __shfl_xor_sync(0xffffffffu, mA, 1));
        mA = fmaxf(mA, __shfl_xor_sync(0xffffffffu, mA, 2));
        mB = fmaxf(mB, __shfl_xor_sync(0xffffffffu, mB, 1));
        mB = fmaxf(mB, __shfl_xor_sync(0xffffffffu, mB, 2));
        float mnA = fmaxf(m0r, mA);
        float mnB = fmaxf(m1r, mB);
        float alA = __expf(m0r - mnA);
        float alB = __expf(m1r - mnB);
        float sumA = 0.0f, sumB = 0.0f;
#pragma unroll
        for (int nt = 0; nt < 8; nt++) {
            float p0 = __expf(sc[nt][0] - mnA);
            float p1 = __expf(sc[nt][1] - mnA);
            float p2 = __expf(sc[nt][2] - mnB);
            float p3 = __expf(sc[nt][3] - mnB);
            sumA += p0 + p1;
            sumB += p2 + p3;
            __nv_bfloat162 hA = __floats2bfloat162_rn(p0, p1);
            __nv_bfloat162 hB = __floats2bfloat162_rn(p2, p3);
            *(uint32_t*)&Ps[qrowA][nt * 8 + qd * 2] = *(uint32_t*)&hA;
            *(uint32_t*)&Ps[qrowB][nt * 8 + qd * 2] = *(uint32_t*)&hB;
        }
        sumA += __shfl_xor_sync(0xffffffffu, sumA, 1);
        sumA += __shfl_xor_sync(0xffffffffu, sumA, 2);
        sumB += __shfl_xor_sync(0xffffffffu, sumB, 1);
        sumB += __shfl_xor_sync(0xffffffffu, sumB, 2);
        l0r = l0r * alA + sumA;
        l1r = l1r * alB + sumB;
        m0r = mnA;
        m1r = mnB;
#pragma unroll
        for (int nt = 0; nt < 8; nt++) {
            o[nt][0] *= alA; o[nt][1] *= alA;
            o[nt][2] *= alB; o[nt][3] *= alB;
        }
        __syncwarp();

#pragma unroll
        for (int ks = 0; ks < 4; ks++) {
            int k0 = ks * 16;
            uint32_t a0 = *(const uint32_t*)&Ps[qrowA][k0 + qd * 2];
            uint32_t a1 = *(const uint32_t*)&Ps[qrowB][k0 + qd * 2];
            uint32_t a2 = *(const uint32_t*)&Ps[qrowA][k0 + qd * 2 + 8];
            uint32_t a3 = *(const uint32_t*)&Ps[qrowB][k0 + qd * 2 + 8];
#pragma unroll
            for (int nt = 0; nt < 8; nt++) {
                uint32_t b0 = *(const uint32_t*)&Vt[nt * 8 + quad][k0 + qd * 2];
                uint32_t b1 = *(const uint32_t*)&Vt[nt * 8 + quad][k0 + qd * 2 + 8];
                mma_bf16(o[nt], a0, a1, a2, a3, b0, b1);
            }
        }
    }

    float* __restrict__ po = g_scratch + OFF_PARTO + (long)split * NN * IN_DIM;
    int gA = q0 + qrowA;
    int gB = q0 + qrowB;
#pragma unroll
    for (int nt = 0; nt < 8; nt++) {
        *(float2*)&po[(size_t)gA * IN_DIM + head * 64 + nt * 8 + qd * 2] =
            make_float2(o[nt][0], o[nt][1]);
        *(float2*)&po[(size_t)gB * IN_DIM + head * 64 + nt * 8 + qd * 2] =
            make_float2(o[nt][2], o[nt][3]);
    }
    if (qd == 0) {
        long mlbase = OFF_PARTML + ((long)split * HEADS + head) * NN;
        long lbase = mlbase + (long)SPLITS * HEADS * NN;
        g_scratch[mlbase + gA] = m0r;
        g_scratch[mlbase + gB] = m1r;
        g_scratch[lbase + gA] = l0r;
        g_scratch[lbase + gB] = l1r;
    }
}

__global__ __launch_bounds__(256) void attn_combine_kernel() {
    int idx = blockIdx.x * 256 + threadIdx.x;
    int dq = idx & 15;
    int h = (idx >> 4) & (HEADS - 1);
    int row = idx >> 6;

    float m[SPLITS], l[SPLITS];
    float M = -1e30f;
#pragma unroll
    for (int s = 0; s < SPLITS; s++) {
        long mlbase = OFF_PARTML + ((long)s * HEADS + h) * NN;
        m[s] = g_scratch[mlbase + row];
        l[s] = g_scratch[mlbase + (long)SPLITS * HEADS * NN + row];
        M = fmaxf(M, m[s]);
    }
    float L = 0.0f;
    float4 acc = make_float4(0.0f, 0.0f, 0.0f, 0.0f);
#pragma unroll
    for (int s = 0; s < SPLITS; s++) {
        float w = __expf(m[s] - M);
        L += l[s] * w;
        const float* po = g_scratch + OFF_PARTO + (long)s * NN * IN_DIM;
        float4 v = *(const float4*)&po[(size_t)row * IN_DIM + h * 64 + dq * 4];
        acc.x += v.x * w; acc.y += v.y * w;
        acc.z += v.z * w; acc.w += v.w * w;
    }
    float inv = 1.0f / L;
    acc.x *= inv; acc.y *= inv; acc.z *= inv; acc.w *= inv;
    *(float4*)&g_scratch[OFF_COMBO + (size_t)row * 768 + 512 + h * 64 + dq * 4] = acc;
}

// ---------------- launch (single stream, sequential) ----------------
extern "C" void kernel_launch(void* const* d_in, const int* in_sizes, int n_in,
                              void* d_out, int out_size) {
    const float* x          = (const float*)d_in[0];
    const int*   ei         = (const int*)d_in[1];
    const float* gcn1_w     = (const float*)d_in[2];
    const float* gcn1_b     = (const float*)d_in[3];
    const float* gcn2_w     = (const float*)d_in[4];
    const float* gcn2_b     = (const float*)d_in[5];
    const float* lin_w      = (const float*)d_in[6];
    const float* lin_b      = (const float*)d_in[7];
    const float* in_proj_w  = (const float*)d_in[8];
    const float* in_proj_b  = (const float*)d_in[9];
    const float* out_proj_w = (const float*)d_in[10];
    const float* out_proj_b = (const float*)d_in[11];
    const float* proj_w     = (const float*)d_in[12];
    const float* proj_b     = (const float*)d_in[13];
    float* out = (float*)d_out;

    // CSR build + dinv (g_cnt starts 0; fill consumes it back to 0)
    hist_kernel<<<EE / 256, 256>>>(ei);
    scan_kernel<<<1, 1024>>>();
    fill_kernel<<<EE / 256, 256>>>(ei);

    // fused weight folding
    fold_kernel<<<385, 256>>>(lin_w, out_proj_w, proj_w, lin_b, out_proj_b, proj_b);

    // transformer: qkv (bf16 out) -> split-K flash attention -> combine
    gemm_tc<true, false, true, true><<<dim3((3 * IN_DIM) / 128, NN / 64), 256>>>(
        x, 0L, in_proj_w, 0L, in_proj_b, 0L, nullptr, 0L, NN, IN_DIM, 3 * IN_DIM);
    flash_attn_split_kernel<<<dim3(NN / 64, HEADS, SPLITS), 128>>>();
    attn_combine_kernel<<<(NN * HEADS * 16) / 256, 256>>>();

    // GNN: aggregate-first conv1
    gather_kernel<false><<<dim3(NN / 8, IN_DIM / 128), 256>>>(
        x, 0L, nullptr, OFF_AGGX, IN_DIM, IN_DIM, 0);
    gemm_tc<false, true, true, false><<<dim3(HIDDEN / 128, NN / 64), 256>>>(
        nullptr, OFF_AGGX, gcn1_w, 0L, gcn1_b, 0L, nullptr, OFF_AGG1, NN, IN_DIM, HIDDEN);

    gemm_tc<false, false, false, false><<<dim3(HIDDEN / 128, NN / 64), 256>>>(
        nullptr, OFF_AGG1, gcn2_w, 0L, nullptr, 0L, nullptr, OFF_H2, NN, HIDDEN, HIDDEN);
    gather_kernel<true><<<dim3(NN / 8, HIDDEN / 128), 256>>>(
        nullptr, OFF_H2, gcn2_b, OFF_COMBO, HIDDEN, 768, 0);

    // out = relu([agg2 | attn] @ comboW + b_tot)
    gemm_tc<false, true, true, false><<<dim3(CLASSES / 128, NN / 64), 256>>>(
        nullptr, OFF_COMBO, nullptr, OFF_COMBOW, nullptr, OFF_BTOT, out, 0L, NN, 768, CLASSES);
}

// round 17
// speedup vs baseline: 1.4001x; 1.0293x over previous
#include <cuda_runtime.h>
#include <cuda_bf16.h>
#include <math.h>
#include <stdint.h>

#define NN 4096
#define IN_DIM 256
#define HIDDEN 512
#define CLASSES 256
#define HEADS 4
#define HD 64
#define EE 131072
#define SPLITS 4

// ---------------- scratch ----------------
#define OFF_DINV   0L
#define OFF_AGGX   (OFF_DINV + NN)
#define OFF_AGG1   (OFF_AGGX + (long)NN * IN_DIM)
#define OFF_H2     (OFF_AGG1 + (long)NN * HIDDEN)
#define OFF_COMBO  (OFF_H2   + (long)NN * HIDDEN)
#define OFF_COMBOW (OFF_COMBO + (long)NN * 768)
#define OFF_BTOT   (OFF_COMBOW + 768L * 256)
#define OFF_PARTO  (OFF_BTOT + 256)
#define OFF_PARTML (OFF_PARTO + (long)SPLITS * NN * IN_DIM)
#define SCRATCH_TOTAL (OFF_PARTML + 2L * SPLITS * HEADS * NN)

__device__ __align__(16) float g_scratch[SCRATCH_TOTAL];
__device__ __align__(16) __nv_bfloat16 g_qkvh[(long)NN * 3 * IN_DIM];
__device__ int g_cnt[NN];         // zero-init; returns to 0 after each full pass
__device__ int g_rowptr[NN + 1];
__device__ int g_srcidx[EE];

// ---------------- CSR build ----------------
__global__ void hist_kernel(const int* __restrict__ ei) {
    int i = blockIdx.x * blockDim.x + threadIdx.x;
    if (i < EE) atomicAdd(&g_cnt[ei[EE + i]], 1);
}
__global__ __launch_bounds__(1024) void scan_kernel() {
    __shared__ int sh[1024];
    int t = threadIdx.x;
    int base = t * 4;
    int c0 = g_cnt[base + 0], c1 = g_cnt[base + 1];
    int c2 = g_cnt[base + 2], c3 = g_cnt[base + 3];
    int s = c0 + c1 + c2 + c3;
    sh[t] = s;
    __syncthreads();
    for (int off = 1; off < 1024; off <<= 1) {
        int v = (t >= off) ? sh[t - off] : 0;
        __syncthreads();
        sh[t] += v;
        __syncthreads();
    }
    int run = sh[t] - s;
    g_rowptr[base + 0] = run;            run += c0;
    g_rowptr[base + 1] = run;            run += c1;
    g_rowptr[base + 2] = run;            run += c2;
    g_rowptr[base + 3] = run;            run += c3;
    if (t == 1023) g_rowptr[NN] = run;
    g_scratch[OFF_DINV + base + 0] = rsqrtf((float)c0 + 1.0f);
    g_scratch[OFF_DINV + base + 1] = rsqrtf((float)c1 + 1.0f);
    g_scratch[OFF_DINV + base + 2] = rsqrtf((float)c2 + 1.0f);
    g_scratch[OFF_DINV + base + 3] = rsqrtf((float)c3 + 1.0f);
}
__global__ void fill_kernel(const int* __restrict__ ei) {
    int e = blockIdx.x * blockDim.x + threadIdx.x;
    if (e >= EE) return;
    int dst = ei[EE + e];
    int pos = g_rowptr[dst] + atomicSub(&g_cnt[dst], 1) - 1;
    g_srcidx[pos] = ei[e];
}

// ---------------- fused GCN aggregation (gather) ----------------
template <bool BIASRELU>
__global__ __launch_bounds__(256) void gather_kernel(const float* __restrict__ hext, long hoff,
                                                     const float* __restrict__ bias,
                                                     long aggoff, int F, int ostride, int coloff) {
    const float* __restrict__ h = hext ? hext : (const float*)(g_scratch + hoff);
    float* __restrict__ agg = g_scratch + aggoff;
    const float* __restrict__ dinv = g_scratch + OFF_DINV;
    const int warp = threadIdx.x >> 5;
    const int lane = threadIdx.x & 31;
    const int node = blockIdx.x * 8 + warp;
    const int c = blockIdx.y * 128 + lane * 4;

    float dd = dinv[node];
    float4 hv = *(const float4*)&h[(size_t)node * F + c];
    float sw = dd * dd;
    float4 acc = make_float4(hv.x * sw, hv.y * sw, hv.z * sw, hv.w * sw);
    if (BIASRELU) {
        float4 b4 = *(const float4*)&bias[c];
        acc.x += b4.x; acc.y += b4.y; acc.z += b4.z; acc.w += b4.w;
    }

    int beg = g_rowptr[node];
    int end = g_rowptr[node + 1];
    int j = beg;
    for (; j + 4 <= end; j += 4) {
        int s0 = g_srcidx[j], s1 = g_srcidx[j + 1];
        int s2 = g_srcidx[j + 2], s3 = g_srcidx[j + 3];
        float w0 = dinv[s0] * dd, w1 = dinv[s1] * dd;
        float w2 = dinv[s2] * dd, w3 = dinv[s3] * dd;
        float4 v0 = *(const float4*)&h[(size_t)s0 * F + c];
        float4 v1 = *(const float4*)&h[(size_t)s1 * F + c];
        float4 v2 = *(const float4*)&h[(size_t)s2 * F + c];
        float4 v3 = *(const float4*)&h[(size_t)s3 * F + c];
        acc.x += v0.x * w0 + v1.x * w1 + v2.x * w2 + v3.x * w3;
        acc.y += v0.y * w0 + v1.y * w1 + v2.y * w2 + v3.y * w3;
        acc.z += v0.z * w0 + v1.z * w1 + v2.z * w2 + v3.z * w3;
        acc.w += v0.w * w0 + v1.w * w1 + v2.w * w2 + v3.w * w3;
    }
    for (; j < end; j++) {
        int s0 = g_srcidx[j];
        float w0 = dinv[s0] * dd;
        float4 v0 = *(const float4*)&h[(size_t)s0 * F + c];
        acc.x += v0.x * w0; acc.y += v0.y * w0;
        acc.z += v0.z * w0; acc.w += v0.w * w0;
    }
    if (BIASRELU) {
        acc.x = fmaxf(acc.x, 0.0f); acc.y = fmaxf(acc.y, 0.0f);
        acc.z = fmaxf(acc.z, 0.0f); acc.w = fmaxf(acc.w, 0.0f);
    }
    *(float4*)&agg[(size_t)node * ostride + coloff + c] = acc;
}

// ---------------- fused weight-fold kernel ----------------
// blocks 0..127: copy lin_w chunk; 128..383: wprime row (smem-staged, 4 accums);
// 384: btot (smem-staged)
__global__ __launch_bounds__(256) void fold_kernel(const float* __restrict__ lin_w,
                                                   const float* __restrict__ out_w,
                                                   const float* __restrict__ proj_w,
                                                   const float* __restrict__ lin_b,
                                                   const float* __restrict__ out_b,
                                                   const float* __restrict__ proj_b) {
    int bid = blockIdx.x;
    int t = threadIdx.x;
    if (bid < 128) {
        int i = bid * 256 + t;  // over 512*256/4 = 32768 float4s
        float4 v = *(const float4*)&lin_w[4L * i];
        *(float4*)&g_scratch[OFF_COMBOW + 4L * i] = v;
        return;
    }
    __shared__ float aw[256];
    if (bid < 384) {
        int i = bid - 128;
        aw[t] = out_w[t * 256 + i];   // column i of out_w
        __syncthreads();
        float a0 = 0.0f, a1 = 0.0f, a2 = 0.0f, a3 = 0.0f;
#pragma unroll 2
        for (int k = 0; k < 256; k += 4) {
            a0 += aw[k + 0] * proj_w[(k + 0) * 256 + t];
            a1 += aw[k + 1] * proj_w[(k + 1) * 256 + t];
            a2 += aw[k + 2] * proj_w[(k + 2) * 256 + t];
            a3 += aw[k + 3] * proj_w[(k + 3) * 256 + t];
        }
        g_scratch[OFF_COMBOW + (512L + i) * 256 + t] = (a0 + a1) + (a2 + a3);
    } else {
        aw[t] = out_b[t];
        __syncthreads();
        float a0 = 0.0f, a1 = 0.0f, a2 = 0.0f, a3 = 0.0f;
#pragma unroll 2
        for (int k = 0; k < 256; k += 4) {
            a0 += aw[k + 0] * proj_w[(k + 0) * 256 + t];
            a1 += aw[k + 1] * proj_w[(k + 1) * 256 + t];
            a2 += aw[k + 2] * proj_w[(k + 2) * 256 + t];
            a3 += aw[k + 3] * proj_w[(k + 3) * 256 + t];
        }
        g_scratch[OFF_BTOT + t] = lin_b[t] + proj_b[t] + (a0 + a1) + (a2 + a3);
    }
}

// ---------------- tf32 helpers ----------------
__device__ __forceinline__ float to_tf32(float x) {
    float r;
    asm("cvt.rna.tf32.f32 %0, %1;" : "=f"(r) : "f"(x));
    return r;
}
__device__ __forceinline__ void mma_tf32(float c[4], float a0, float a1, float a2,
                                         float a3, float b0, float b1) {
    uint32_t ua0 = __float_as_uint(a0), ua1 = __float_as_uint(a1);
    uint32_t ua2 = __float_as_uint(a2), ua3 = __float_as_uint(a3);
    uint32_t ub0 = __float_as_uint(b0), ub1 = __float_as_uint(b1);
    asm volatile(
        "mma.sync.aligned.m16n8k8.row.col.f32.tf32.tf32.f32 "
        "{%0,%1,%2,%3},{%4,%5,%6,%7},{%8,%9},{%0,%1,%2,%3};\n"
        : "+f"(c[0]), "+f"(c[1]), "+f"(c[2]), "+f"(c[3])
        : "r"(ua0), "r"(ua1), "r"(ua2), "r"(ua3), "r"(ub0), "r"(ub1));
}

// ---------------- tf32 GEMM: BM=64 BN=128 BK=16, 8 warps (2x4) ----------------
#define AP 20
#define BPN 132
#define BPT 20
template <bool TRANSB, bool RELU, bool HASBIAS, bool OUTBF16>
__global__ __launch_bounds__(256) void gemm_tc(const float* __restrict__ Aext, long aoff,
                                               const float* __restrict__ Bext, long boff,
                                               const float* __restrict__ biasext, long biasoff,
                                               float* __restrict__ Cext, long coff,
                                               int M, int K, int Nd) {
    const float* __restrict__ A = Aext ? Aext : (const float*)(g_scratch + aoff);
    const float* __restrict__ B = Bext ? Bext : (const float*)(g_scratch + boff);
    const float* __restrict__ bias = HASBIAS ? (biasext ? biasext : (const float*)(g_scratch + biasoff)) : nullptr;
    float* __restrict__ C = Cext ? Cext : (g_scratch + coff);

    constexpr int BSZ = TRANSB ? 128 * BPT : 16 * BPN;
    __shared__ float As[2][64][AP];
    __shared__ float Bs[2][BSZ];

    const int tid = threadIdx.x;
    const int warp = tid >> 5, lane = tid & 31;
    const int fr = lane >> 2, fc = lane & 3;
    const int wr = warp >> 2;           // 0..1
    const int wc = warp & 3;            // 0..3
    const int mw = wr * 32;
    const int nw = wc * 32;
    const int m0 = blockIdx.y * 64, n0 = blockIdx.x * 128;

    const int am = tid >> 2;            // 0..63
    const int akq = (tid & 3) * 4;

    float4 pa0, pb0, pb1;
    {
        pa0 = *(const float4*)(A + (size_t)(m0 + am) * K + akq);
        if (TRANSB) {
            int n_0 = tid >> 2, kq = (tid & 3) * 4;
            int n_1 = (256 + tid) >> 2;
            pb0 = *(const float4*)(B + (size_t)(n0 + n_0) * K + kq);
            pb1 = *(const float4*)(B + (size_t)(n0 + n_1) * K + kq);
        } else {
            int r_0 = tid >> 5, c4_0 = (tid & 31) * 4;
            int r_1 = (256 + tid) >> 5, c4_1 = ((256 + tid) & 31) * 4;
            pb0 = *(const float4*)(B + (size_t)r_0 * Nd + n0 + c4_0);
            pb1 = *(const float4*)(B + (size_t)r_1 * Nd + n0 + c4_1);
        }
    }

    float acc[2][4][4];
#pragma unroll
    for (int mf = 0; mf < 2; mf++)
#pragma unroll
        for (int nt = 0; nt < 4; nt++)
#pragma unroll
            for (int j = 0; j < 4; j++) acc[mf][nt][j] = 0.0f;

    const int nk = K >> 4;

    {
        As[0][am][akq + 0] = to_tf32(pa0.x);
        As[0][am][akq + 1] = to_tf32(pa0.y);
        As[0][am][akq + 2] = to_tf32(pa0.z);
        As[0][am][akq + 3] = to_tf32(pa0.w);
        if (TRANSB) {
            int n_0 = tid >> 2, kq = (tid & 3) * 4;
            int n_1 = (256 + tid) >> 2;
            float* p0 = &Bs[0][n_0 * BPT + kq];
            float* p1 = &Bs[0][n_1 * BPT + kq];
            p0[0] = to_tf32(pb0.x); p0[1] = to_tf32(pb0.y);
            p0[2] = to_tf32(pb0.z); p0[3] = to_tf32(pb0.w);
            p1[0] = to_tf32(pb1.x); p1[1] = to_tf32(pb1.y);
            p1[2] = to_tf32(pb1.z); p1[3] = to_tf32(pb1.w);
        } else {
            int r_0 = tid >> 5, c4_0 = (tid & 31) * 4;
            int r_1 = (256 + tid) >> 5, c4_1 = ((256 + tid) & 31) * 4;
            float* p0 = &Bs[0][r_0 * BPN + c4_0];
            float* p1 = &Bs[0][r_1 * BPN + c4_1];
            p0[0] = to_tf32(pb0.x); p0[1] = to_tf32(pb0.y);
            p0[2] = to_tf32(pb0.z); p0[3] = to_tf32(pb0.w);
            p1[0] = to_tf32(pb1.x); p1[1] = to_tf32(pb1.y);
            p1[2] = to_tf32(pb1.z); p1[3] = to_tf32(pb1.w);
        }
    }
    __syncthreads();

    for (int k0i = 0; k0i < nk; k0i++) {
        const int cur = k0i & 1, nxt = cur ^ 1;
        const bool more = (k0i + 1) < nk;
        if (more) {
            int k0 = (k0i + 1) << 4;
            pa0 = *(const float4*)(A + (size_t)(m0 + am) * K + k0 + akq);
            if (TRANSB) {
                int n_0 = tid >> 2, kq = (tid & 3) * 4;
                int n_1 = (256 + tid) >> 2;
                pb0 = *(const float4*)(B + (size_t)(n0 + n_0) * K + k0 + kq);
                pb1 = *(const float4*)(B + (size_t)(n0 + n_1) * K + k0 + kq);
            } else {
                int r_0 = tid >> 5, c4_0 = (tid & 31) * 4;
                int r_1 = (256 + tid) >> 5, c4_1 = ((256 + tid) & 31) * 4;
                pb0 = *(const float4*)(B + (size_t)(k0 + r_0) * Nd + n0 + c4_0);
                pb1 = *(const float4*)(B + (size_t)(k0 + r_1) * Nd + n0 + c4_1);
            }
        }

#pragma unroll
        for (int ks = 0; ks < 2; ks++) {
            int kk = ks * 8;
            float a[2][4];
#pragma unroll
            for (int mf = 0; mf < 2; mf++) {
                int row = mw + mf * 16 + fr;
                a[mf][0] = As[cur][row][kk + fc];
                a[mf][1] = As[cur][row + 8][kk + fc];
                a[mf][2] = As[cur][row][kk + fc + 4];
                a[mf][3] = As[cur][row + 8][kk + fc + 4];
            }
#pragma unroll
            for (int nt = 0; nt < 4; nt++) {
                float b0, b1;
                if (TRANSB) {
                    b0 = Bs[cur][(nw + nt * 8 + fr) * BPT + kk + fc];
                    b1 = Bs[cur][(nw + nt * 8 + fr) * BPT + kk + fc + 4];
                } else {
                    b0 = Bs[cur][(kk + fc) * BPN + nw + nt * 8 + fr];
                    b1 = Bs[cur][(kk + fc + 4) * BPN + nw + nt * 8 + fr];
                }
                mma_tf32(acc[0][nt], a[0][0], a[0][1], a[0][2], a[0][3], b0, b1);
                mma_tf32(acc[1][nt], a[1][0], a[1][1], a[1][2], a[1][3], b0, b1);
            }
        }

        if (more) {
            As[nxt][am][akq + 0] = to_tf32(pa0.x);
            As[nxt][am][akq + 1] = to_tf32(pa0.y);
            As[nxt][am][akq + 2] = to_tf32(pa0.z);
            As[nxt][am][akq + 3] = to_tf32(pa0.w);
            if (TRANSB) {
                int n_0 = tid >> 2, kq = (tid & 3) * 4;
                int n_1 = (256 + tid) >> 2;
                float* p0 = &Bs[nxt][n_0 * BPT + kq];
                float* p1 = &Bs[nxt][n_1 * BPT + kq];
                p0[0] = to_tf32(pb0.x); p0[1] = to_tf32(pb0.y);
                p0[2] = to_tf32(pb0.z); p0[3] = to_tf32(pb0.w);
                p1[0] = to_tf32(pb1.x); p1[1] = to_tf32(pb1.y);
                p1[2] = to_tf32(pb1.z); p1[3] = to_tf32(pb1.w);
            } else {
                int r_0 = tid >> 5, c4_0 = (tid & 31) * 4;
                int r_1 = (256 + tid) >> 5, c4_1 = ((256 + tid) & 31) * 4;
                float* p0 = &Bs[nxt][r_0 * BPN + c4_0];
                float* p1 = &Bs[nxt][r_1 * BPN + c4_1];
                p0[0] = to_tf32(pb0.x); p0[1] = to_tf32(pb0.y);
                p0[2] = to_tf32(pb0.z); p0[3] = to_tf32(pb0.w);
                p1[0] = to_tf32(pb1.x); p1[1] = to_tf32(pb1.y);
                p1[2] = to_tf32(pb1.z); p1[3] = to_tf32(pb1.w);
            }
            __syncthreads();
        }
    }

    // epilogue
#pragma unroll
    for (int mf = 0; mf < 2; mf++) {
        int r0 = m0 + mw + mf * 16 + fr;
        int r1 = r0 + 8;
#pragma unroll
        for (int nt = 0; nt < 4; nt++) {
            int cc = n0 + nw + nt * 8 + fc * 2;
            float v00 = acc[mf][nt][0], v01 = acc[mf][nt][1];
            float v10 = acc[mf][nt][2], v11 = acc[mf][nt][3];
            if (HASBIAS) {
                float b0 = bias[cc], b1 = bias[cc + 1];
                v00 += b0; v01 += b1; v10 += b0; v11 += b1;
            }
            if (RELU) {
                v00 = fmaxf(v00, 0.0f); v01 = fmaxf(v01, 0.0f);
                v10 = fmaxf(v10, 0.0f); v11 = fmaxf(v11, 0.0f);
            }
            if (OUTBF16) {
                __nv_bfloat162 h0 = __floats2bfloat162_rn(v00, v01);
                __nv_bfloat162 h1 = __floats2bfloat162_rn(v10, v11);
                *(uint32_t*)&g_qkvh[(size_t)r0 * Nd + cc] = *(uint32_t*)&h0;
                *(uint32_t*)&g_qkvh[(size_t)r1 * Nd + cc] = *(uint32_t*)&h1;
            } else {
                *(float2*)&C[(size_t)r0 * Nd + cc] = make_float2(v00, v01);
                *(float2*)&C[(size_t)r1 * Nd + cc] = make_float2(v10, v11);
            }
        }
    }
}

// ---------------- bf16 tensor-core flash attention (split-K) ----------------
__device__ __forceinline__ void mma_bf16(float c[4], uint32_t a0, uint32_t a1,
                                         uint32_t a2, uint32_t a3,
                                         uint32_t b0, uint32_t b1) {
    asm volatile(
        "mma.sync.aligned.m16n8k16.row.col.f32.bf16.bf16.f32 "
        "{%0,%1,%2,%3},{%4,%5,%6,%7},{%8,%9},{%0,%1,%2,%3};\n"
        : "+f"(c[0]), "+f"(c[1]), "+f"(c[2]), "+f"(c[3])
        : "r"(a0), "r"(a1), "r"(a2), "r"(a3), "r"(b0), "r"(b1));
}

#define FA_PITCH 72
#define KB_PER_SPLIT (NN / 64 / SPLITS)  // 16

__global__ __launch_bounds__(128) void flash_attn_split_kernel() {
    const __nv_bfloat16* __restrict__ qkvh = g_qkvh;
    const int head = blockIdx.y;
    const int split = blockIdx.z;
    const int q0 = blockIdx.x * 64;
    const int tid = threadIdx.x;
    const int warp = tid >> 5;
    const int lane = tid & 31;
    const int quad = lane >> 2;
    const int qd = lane & 3;

    __shared__ __align__(16) __nv_bfloat16 Qs[64][FA_PITCH];
    __shared__ __align__(16) __nv_bfloat16 Ks[64][FA_PITCH];
    __shared__ __align__(16) __nv_bfloat16 Vt[64][FA_PITCH];
    __shared__ __align__(16) __nv_bfloat16 Ps[64][FA_PITCH];

#pragma unroll
    for (int ch = 0; ch < 4; ch++) {
        int idx = ch * 128 + tid;
        int r = idx >> 3;
        int c = (idx & 7) * 8;
        *(uint4*)&Qs[r][c] =
            *(const uint4*)&qkvh[(size_t)(q0 + r) * 768 + head * 64 + c];
    }

    float m0r = -1e30f, m1r = -1e30f;
    float l0r = 0.0f, l1r = 0.0f;
    float o[8][4];
#pragma unroll
    for (int nt = 0; nt < 8; nt++)
#pragma unroll
        for (int j = 0; j < 4; j++) o[nt][j] = 0.0f;

    const int qrowA = warp * 16 + quad;
    const int qrowB = qrowA + 8;

    const int kb_beg = split * KB_PER_SPLIT;
    for (int kb = kb_beg; kb < kb_beg + KB_PER_SPLIT; kb++) {
        int kbase = kb * 64;
        __syncthreads();
#pragma unroll
        for (int ch = 0; ch < 4; ch++) {
            int idx = ch * 128 + tid;
            int r = idx >> 3;
            int c = (idx & 7) * 8;
            *(uint4*)&Ks[r][c] =
                *(const uint4*)&qkvh[(size_t)(kbase + r) * 768 + 256 + head * 64 + c];
        }
        {
            int r = tid & 63;
            int d0 = (tid >> 6) * 32;
#pragma unroll
            for (int u = 0; u < 4; u++) {
                uint4 vv = *(const uint4*)&qkvh[(size_t)(kbase + r) * 768 + 512 +
                                                head * 64 + d0 + u * 8];
                __nv_bfloat16 tmp[8];
                *(uint4*)tmp = vv;
#pragma unroll
                for (int j = 0; j < 8; j++) Vt[d0 + u * 8 + j][r] = tmp[j];
            }
        }
        __syncthreads();

        float sc[8][4];
#pragma unroll
        for (int nt = 0; nt < 8; nt++)
#pragma unroll
            for (int j = 0; j < 4; j++) sc[nt][j] = 0.0f;

#pragma unroll
        for (int ks = 0; ks < 4; ks++) {
            int k0 = ks * 16;
            uint32_t a0 = *(const uint32_t*)&Qs[qrowA][k0 + qd * 2];
            uint32_t a1 = *(const uint32_t*)&Qs[qrowB][k0 + qd * 2];
            uint32_t a2 = *(const uint32_t*)&Qs[qrowA][k0 + qd * 2 + 8];
            uint32_t a3 = *(const uint32_t*)&Qs[qrowB][k0 + qd * 2 + 8];
#pragma unroll
            for (int nt = 0; nt < 8; nt++) {
                uint32_t b0 = *(const uint32_t*)&Ks[nt * 8 + quad][k0 + qd * 2];
                uint32_t b1 = *(const uint32_t*)&Ks[nt * 8 + quad][k0 + qd * 2 + 8];
                mma_bf16(sc[nt], a0, a1, a2, a3, b0, b1);
            }
        }

        float mA = -1e30f, mB = -1e30f;
#pragma unroll
        for (int nt = 0; nt < 8; nt++) {
            sc[nt][0] *= 0.125f; sc[nt][1] *= 0.125f;
            sc[nt][2] *= 0.125f; sc[nt][3] *= 0.125f;
            mA = fmaxf(mA, fmaxf(sc[nt][0], sc[nt][1]));
            mB = fmaxf(mB, fmaxf(sc[nt][2], sc[nt][3]));
        }
        mA = fmaxf(mA, __shfl_xor_sync(0xffffffffu, mA, 1));
        mA = fmaxf(mA, __shfl_xor_sync(0xffffffffu, mA, 2));
        mB = fmaxf(mB, __shfl_xor_sync(0xffffffffu, mB, 1));
        mB = fmaxf(mB, __shfl_xor_sync(0xffffffffu, mB, 2));
        float mnA = fmaxf(m0r, mA);
        float mnB = fmaxf(m1r, mB);
        float alA = __expf(m0r - mnA);
        float alB = __expf(m1r - mnB);
        float sumA = 0.0f, sumB = 0.0f;
#pragma unroll
        for (int nt = 0; nt < 8; nt++) {
            float p0 = __expf(sc[nt][0] - mnA);
            float p1 = __expf(sc[nt][1] - mnA);
            float p2 = __expf(sc[nt][2] - mnB);
            float p3 = __expf(sc[nt][3] - mnB);
            sumA += p0 + p1;
            sumB += p2 + p3;
            __nv_bfloat162 hA = __floats2bfloat162_rn(p0, p1);
            __nv_bfloat162 hB = __floats2bfloat162_rn(p2, p3);
            *(uint32_t*)&Ps[qrowA][nt * 8 + qd * 2] = *(uint32_t*)&hA;
            *(uint32_t*)&Ps[qrowB][nt * 8 + qd * 2] = *(uint32_t*)&hB;
        }
        sumA += __shfl_xor_sync(0xffffffffu, sumA, 1);
        sumA += __shfl_xor_sync(0xffffffffu, sumA, 2);
        sumB += __shfl_xor_sync(0xffffffffu, sumB, 1);
        sumB += __shfl_xor_sync(0xffffffffu, sumB, 2);
        l0r = l0r * alA + sumA;
        l1r = l1r * alB + sumB;
        m0r = mnA;
        m1r = mnB;
#pragma unroll
        for (int nt = 0; nt < 8; nt++) {
            o[nt][0] *= alA; o[nt][1] *= alA;
            o[nt][2] *= alB; o[nt][3] *= alB;
        }
        __syncwarp();

#pragma unroll
        for (int ks = 0; ks < 4; ks++) {
            int k0 = ks * 16;
            uint32_t a0 = *(const uint32_t*)&Ps[qrowA][k0 + qd * 2];
            uint32_t a1 = *(const uint32_t*)&Ps[qrowB][k0 + qd * 2];
            uint32_t a2 = *(const uint32_t*)&Ps[qrowA][k0 + qd * 2 + 8];
            uint32_t a3 = *(const uint32_t*)&Ps[qrowB][k0 + qd * 2 + 8];
#pragma unroll
            for (int nt = 0; nt < 8; nt++) {
                uint32_t b0 = *(const uint32_t*)&Vt[nt * 8 + quad][k0 + qd * 2];
                uint32_t b1 = *(const uint32_t*)&Vt[nt * 8 + quad][k0 + qd * 2 + 8];
                mma_bf16(o[nt], a0, a1, a2, a3, b0, b1);
            }
        }
    }

    float* __restrict__ po = g_scratch + OFF_PARTO + (long)split * NN * IN_DIM;
    int gA = q0 + qrowA;
    int gB = q0 + qrowB;
#pragma unroll
    for (int nt = 0; nt < 8; nt++) {
        *(float2*)&po[(size_t)gA * IN_DIM + head * 64 + nt * 8 + qd * 2] =
            make_float2(o[nt][0], o[nt][1]);
        *(float2*)&po[(size_t)gB * IN_DIM + head * 64 + nt * 8 + qd * 2] =
            make_float2(o[nt][2], o[nt][3]);
    }
    if (qd == 0) {
        long mlbase = OFF_PARTML + ((long)split * HEADS + head) * NN;
        long lbase = mlbase + (long)SPLITS * HEADS * NN;
        g_scratch[mlbase + gA] = m0r;
        g_scratch[mlbase + gB] = m1r;
        g_scratch[lbase + gA] = l0r;
        g_scratch[lbase + gB] = l1r;
    }
}

__global__ __launch_bounds__(256) void attn_combine_kernel() {
    int idx = blockIdx.x * 256 + threadIdx.x;
    int dq = idx & 15;
    int h = (idx >> 4) & (HEADS - 1);
    int row = idx >> 6;

    float m[SPLITS], l[SPLITS];
    float M = -1e30f;
#pragma unroll
    for (int s = 0; s < SPLITS; s++) {
        long mlbase = OFF_PARTML + ((long)s * HEADS + h) * NN;
        m[s] = g_scratch[mlbase + row];
        l[s] = g_scratch[mlbase + (long)SPLITS * HEADS * NN + row];
        M = fmaxf(M, m[s]);
    }
    float L = 0.0f;
    float4 acc = make_float4(0.0f, 0.0f, 0.0f, 0.0f);
#pragma unroll
    for (int s = 0; s < SPLITS; s++) {
        float w = __expf(m[s] - M);
        L += l[s] * w;
        const float* po = g_scratch + OFF_PARTO + (long)s * NN * IN_DIM;
        float4 v = *(const float4*)&po[(size_t)row * IN_DIM + h * 64 + dq * 4];
        acc.x += v.x * w; acc.y += v.y * w;
        acc.z += v.z * w; acc.w += v.w * w;
    }
    float inv = 1.0f / L;
    acc.x *= inv; acc.y *= inv; acc.z *= inv; acc.w *= inv;
    *(float4*)&g_scratch[OFF_COMBO + (size_t)row * 768 + 512 + h * 64 + dq * 4] = acc;
}

// ---------------- launch (single stream, sequential) ----------------
extern "C" void kernel_launch(void* const* d_in, const int* in_sizes, int n_in,
                              void* d_out, int out_size) {
    const float* x          = (const float*)d_in[0];
    const int*   ei         = (const int*)d_in[1];
    const float* gcn1_w     = (const float*)d_in[2];
    const float* gcn1_b     = (const float*)d_in[3];
    const float* gcn2_w     = (const float*)d_in[4];
    const float* gcn2_b     = (const float*)d_in[5];
    const float* lin_w      = (const float*)d_in[6];
    const float* lin_b      = (const float*)d_in[7];
    const float* in_proj_w  = (const float*)d_in[8];
    const float* in_proj_b  = (const float*)d_in[9];
    const float* out_proj_w = (const float*)d_in[10];
    const float* out_proj_b = (const float*)d_in[11];
    const float* proj_w     = (const float*)d_in[12];
    const float* proj_b     = (const float*)d_in[13];
    float* out = (float*)d_out;

    // CSR build + dinv (g_cnt starts 0; fill consumes it back to 0)
    hist_kernel<<<EE / 256, 256>>>(ei);
    scan_kernel<<<1, 1024>>>();
    fill_kernel<<<EE / 256, 256>>>(ei);

    // fused weight folding
    fold_kernel<<<385, 256>>>(lin_w, out_proj_w, proj_w, lin_b, out_proj_b, proj_b);

    // transformer: qkv (bf16 out) -> split-K flash attention -> combine
    gemm_tc<true, false, true, true><<<dim3((3 * IN_DIM) / 128, NN / 64), 256>>>(
        x, 0L, in_proj_w, 0L, in_proj_b, 0L, nullptr, 0L, NN, IN_DIM, 3 * IN_DIM);
    flash_attn_split_kernel<<<dim3(NN / 64, HEADS, SPLITS), 128>>>();
    attn_combine_kernel<<<(NN * HEADS * 16) / 256, 256>>>();

    // GNN: aggregate-first conv1
    gather_kernel<false><<<dim3(NN / 8, IN_DIM / 128), 256>>>(
        x, 0L, nullptr, OFF_AGGX, IN_DIM, IN_DIM, 0);
    gemm_tc<false, true, true, false><<<dim3(HIDDEN / 128, NN / 64), 256>>>(
        nullptr, OFF_AGGX, gcn1_w, 0L, gcn1_b, 0L, nullptr, OFF_AGG1, NN, IN_DIM, HIDDEN);

    gemm_tc<false, false, false, false><<<dim3(HIDDEN / 128, NN / 64), 256>>>(
        nullptr, OFF_AGG1, gcn2_w, 0L, nullptr, 0L, nullptr, OFF_H2, NN, HIDDEN, HIDDEN);
    gather_kernel<true><<<dim3(NN / 8, HIDDEN / 128), 256>>>(
        nullptr, OFF_H2, gcn2_b, OFF_COMBO, HIDDEN, 768, 0);

    // out = relu([agg2 | attn] @ comboW + b_tot)
    gemm_tc<false, true, true, false><<<dim3(CLASSES / 128, NN / 64), 256>>>(
        nullptr, OFF_COMBO, nullptr, OFF_COMBOW, nullptr, OFF_BTOT, out, 0L, NN, 768, CLASSES);
}